// round 1
// baseline (speedup 1.0000x reference)
#include <cuda_runtime.h>
#include <math.h>

#define E_DIM 1024
#define NHEAD 16
#define HDIM  64
#define BATCH 2
#define SEQ   2048
#define MROWS (BATCH * SEQ)   // 4096

// ---------------- scratch (static device globals: allocation-guard safe) ----
__device__ float g_qkv[(size_t)MROWS * 3 * E_DIM];  // 50 MB
__device__ float g_q  [(size_t)MROWS * E_DIM];      // 16 MB
__device__ float g_k  [(size_t)MROWS * E_DIM];      // 16 MB
__device__ float g_o  [(size_t)MROWS * E_DIM];      // 16 MB

// ---------------- tiled SGEMM -----------------------------------------------
// C[m,n] = sum_k A[m,k] * B'[k,n]  (+bias[n]) (+res[m,n])
//   BNT=1: B is (N,K) row-major  -> B'[k,n] = B[n*ldb + k]   (torch Linear W)
//   BNT=0: B is (K,N) row-major  -> B'[k,n] = B[k*ldb + n]
// BM=BN=128, BK=16, 256 threads, 8x8 per-thread microtile. Dims must divide.
template<int BNT, int BIAS, int RES>
__global__ __launch_bounds__(256)
void sgemm_kernel(const float* __restrict__ A, int lda,
                  const float* __restrict__ B, int ldb,
                  const float* __restrict__ bias,
                  const float* __restrict__ res, int ldr,
                  float* __restrict__ C, int ldc, int K)
{
    __shared__ float As[16][132];  // pad 4 to break store conflicts
    __shared__ float Bs[16][132];

    const int tid = threadIdx.x;
    const int bm = blockIdx.y * 128;
    const int bn = blockIdx.x * 128;
    const int ty = tid >> 4;        // 0..15
    const int tx = tid & 15;        // 0..15

    float acc[8][8];
#pragma unroll
    for (int i = 0; i < 8; i++)
#pragma unroll
        for (int j = 0; j < 8; j++) acc[i][j] = 0.f;

    for (int k0 = 0; k0 < K; k0 += 16) {
        // load A tile: As[k][m]
#pragma unroll
        for (int it = 0; it < 8; it++) {
            int idx = tid + it * 256;          // 0..2047
            int m = idx >> 4, k = idx & 15;
            As[k][m] = A[(size_t)(bm + m) * lda + k0 + k];
        }
        if (BNT) {
#pragma unroll
            for (int it = 0; it < 8; it++) {
                int idx = tid + it * 256;
                int n = idx >> 4, k = idx & 15;
                Bs[k][n] = B[(size_t)(bn + n) * ldb + k0 + k];
            }
        } else {
#pragma unroll
            for (int it = 0; it < 8; it++) {
                int idx = tid + it * 256;
                int k = idx >> 7, n = idx & 127;
                Bs[k][n] = B[(size_t)(k0 + k) * ldb + bn + n];
            }
        }
        __syncthreads();

#pragma unroll
        for (int k = 0; k < 16; k++) {
            float a[8], b[8];
            *(float4*)&a[0] = *(const float4*)&As[k][ty * 8];
            *(float4*)&a[4] = *(const float4*)&As[k][ty * 8 + 4];
            *(float4*)&b[0] = *(const float4*)&Bs[k][tx * 8];
            *(float4*)&b[4] = *(const float4*)&Bs[k][tx * 8 + 4];
#pragma unroll
            for (int i = 0; i < 8; i++)
#pragma unroll
                for (int j = 0; j < 8; j++)
                    acc[i][j] = fmaf(a[i], b[j], acc[i][j]);
        }
        __syncthreads();
    }

#pragma unroll
    for (int i = 0; i < 8; i++) {
        int m = bm + ty * 8 + i;
#pragma unroll
        for (int j = 0; j < 8; j++) {
            int n = bn + tx * 8 + j;
            float v = acc[i][j];
            if (BIAS) v += bias[n];
            if (RES)  v += res[(size_t)m * ldr + n];
            C[(size_t)m * ldc + n] = v;
        }
    }
}

// ---------------- flash attention (fp32, online softmax) --------------------
// grid = (SEQ/128, NHEAD, BATCH), 128 threads; thread t owns q-row (bx*128+t).
// Q,K: row stride E_DIM. V (inside g_qkv): row stride 3*E_DIM.
__global__ __launch_bounds__(128)
void flash_kernel(const float* __restrict__ Q, const float* __restrict__ Kp,
                  const float* __restrict__ V, float* __restrict__ O)
{
    __shared__ float Ks[64][64];
    __shared__ float Vs[64][64];

    const int tid = threadIdx.x;
    const int h = blockIdx.y;
    const int b = blockIdx.z;
    const int qrow = blockIdx.x * 128 + tid;

    const float* qptr = Q + ((size_t)(b * SEQ + qrow)) * E_DIM + h * HDIM;
    float qr[64];
#pragma unroll
    for (int d = 0; d < 64; d += 4) {
        float4 t = *(const float4*)(qptr + d);
        qr[d + 0] = t.x * 0.125f;   // 1/sqrt(64)
        qr[d + 1] = t.y * 0.125f;
        qr[d + 2] = t.z * 0.125f;
        qr[d + 3] = t.w * 0.125f;
    }

    float acc[64];
#pragma unroll
    for (int d = 0; d < 64; d++) acc[d] = 0.f;
    float mi = -1e30f, li = 0.f;

    const float* kbase = Kp + ((size_t)b * SEQ) * E_DIM + h * HDIM;
    const float* vbase = V + ((size_t)b * SEQ) * (3 * E_DIM) + h * HDIM;

    for (int j0 = 0; j0 < SEQ; j0 += 64) {
        __syncthreads();   // protect previous tile's reads
        // load 64x64 K and V tiles: 1024 float4 each, 8 per thread
#pragma unroll
        for (int it = 0; it < 8; it++) {
            int idx4 = tid + it * 128;          // 0..1023
            int row = idx4 >> 4;                // 16 float4 per row
            int c4  = idx4 & 15;
            *(float4*)&Ks[row][c4 * 4] =
                *(const float4*)(kbase + (size_t)(j0 + row) * E_DIM + c4 * 4);
            *(float4*)&Vs[row][c4 * 4] =
                *(const float4*)(vbase + (size_t)(j0 + row) * (3 * E_DIM) + c4 * 4);
        }
        __syncthreads();

#pragma unroll 4
        for (int kk = 0; kk < 64; kk++) {
            const float4* krow = (const float4*)Ks[kk];
            float s = 0.f;
#pragma unroll
            for (int d4 = 0; d4 < 16; d4++) {
                float4 kv = krow[d4];
                s = fmaf(qr[4 * d4 + 0], kv.x, s);
                s = fmaf(qr[4 * d4 + 1], kv.y, s);
                s = fmaf(qr[4 * d4 + 2], kv.z, s);
                s = fmaf(qr[4 * d4 + 3], kv.w, s);
            }
            if (s > mi) {                       // rare after warm-up
                float c = __expf(mi - s);
                mi = s;
                li *= c;
#pragma unroll
                for (int d = 0; d < 64; d++) acc[d] *= c;
            }
            float p = __expf(s - mi);
            li += p;
            const float4* vrow = (const float4*)Vs[kk];
#pragma unroll
            for (int d4 = 0; d4 < 16; d4++) {
                float4 vv = vrow[d4];
                acc[4 * d4 + 0] = fmaf(p, vv.x, acc[4 * d4 + 0]);
                acc[4 * d4 + 1] = fmaf(p, vv.y, acc[4 * d4 + 1]);
                acc[4 * d4 + 2] = fmaf(p, vv.z, acc[4 * d4 + 2]);
                acc[4 * d4 + 3] = fmaf(p, vv.w, acc[4 * d4 + 3]);
            }
        }
    }

    float inv = 1.f / li;
    float* optr = O + ((size_t)(b * SEQ + qrow)) * E_DIM + h * HDIM;
#pragma unroll
    for (int d = 0; d < 64; d += 4) {
        float4 t;
        t.x = acc[d + 0] * inv;
        t.y = acc[d + 1] * inv;
        t.z = acc[d + 2] * inv;
        t.w = acc[d + 3] * inv;
        *(float4*)(optr + d) = t;
    }
}

// ---------------- launcher ---------------------------------------------------
extern "C" void kernel_launch(void* const* d_in, const int* in_sizes, int n_in,
                              void* d_out, int out_size)
{
    (void)in_sizes; (void)n_in; (void)out_size;
    const float* x    = (const float*)d_in[0];
    const float* rot  = (const float*)d_in[1];
    const float* ent  = (const float*)d_in[2];
    const float* qkvw = (const float*)d_in[3];
    const float* qkvb = (const float*)d_in[4];
    const float* outw = (const float*)d_in[5];
    const float* outb = (const float*)d_in[6];
    float* out = (float*)d_out;

    float *qkv, *q, *k, *o;
    cudaGetSymbolAddress((void**)&qkv, g_qkv);
    cudaGetSymbolAddress((void**)&q,   g_q);
    cudaGetSymbolAddress((void**)&k,   g_k);
    cudaGetSymbolAddress((void**)&o,   g_o);

    // 1) qkv = x @ qkv_w^T + qkv_b        (4096 x 3072 x 1024, NT)
    sgemm_kernel<1, 1, 0><<<dim3(3 * E_DIM / 128, MROWS / 128), 256>>>(
        x, E_DIM, qkvw, E_DIM, qkvb, nullptr, 0, qkv, 3 * E_DIM, E_DIM);

    // 2) q' = qkv[:, 0:1024] @ rotation   (NN)
    sgemm_kernel<0, 0, 0><<<dim3(E_DIM / 128, MROWS / 128), 256>>>(
        qkv, 3 * E_DIM, rot, E_DIM, nullptr, nullptr, 0, q, E_DIM, E_DIM);

    // 3) k' = qkv[:, 1024:2048] @ entangle (NN)
    sgemm_kernel<0, 0, 0><<<dim3(E_DIM / 128, MROWS / 128), 256>>>(
        qkv + E_DIM, 3 * E_DIM, ent, E_DIM, nullptr, nullptr, 0, k, E_DIM, E_DIM);

    // 4) attention: O = softmax(q' k'^T / 8) @ v   (v = qkv[:, 2048:], stride 3E)
    flash_kernel<<<dim3(SEQ / 128, NHEAD, BATCH), 128>>>(
        q, k, qkv + 2 * E_DIM, o);

    // 5) out = O @ out_w^T + out_b + x    (NT + bias + residual)
    sgemm_kernel<1, 1, 1><<<dim3(E_DIM / 128, MROWS / 128), 256>>>(
        o, E_DIM, outw, E_DIM, outb, x, E_DIM, out, E_DIM, E_DIM);
}

// round 4
// speedup vs baseline: 1.1874x; 1.1874x over previous
#include <cuda_runtime.h>
#include <cuda_bf16.h>
#include <cstdint>
#include <math.h>

#define E_DIM 1024
#define NHEAD 16
#define HDIM  64
#define BATCH 2
#define SEQ   2048
#define MROWS (BATCH * SEQ)   // 4096

// ---------------- scratch (static device globals: allocation-guard safe) ----
__device__ float g_qkv[(size_t)MROWS * 3 * E_DIM];
__device__ float g_q  [(size_t)MROWS * E_DIM];
__device__ float g_k  [(size_t)MROWS * E_DIM];
__device__ float g_o  [(size_t)MROWS * E_DIM];

// ======================= mma.sync helpers (sm_80+ path, valid on sm_103) ====
__device__ __forceinline__ uint32_t smem_u32(const void* p) {
    uint32_t a;
    asm("{ .reg .u64 t; cvta.to.shared.u64 t, %1; cvt.u32.u64 %0, t; }" : "=r"(a) : "l"(p));
    return a;
}
__device__ __forceinline__ void ldsm_x4(uint32_t* r, uint32_t addr) {
    asm volatile("ldmatrix.sync.aligned.m8n8.x4.shared.b16 {%0,%1,%2,%3}, [%4];"
                 : "=r"(r[0]), "=r"(r[1]), "=r"(r[2]), "=r"(r[3]) : "r"(addr));
}
__device__ __forceinline__ void ldsm_x2(uint32_t* r, uint32_t addr) {
    asm volatile("ldmatrix.sync.aligned.m8n8.x2.shared.b16 {%0,%1}, [%2];"
                 : "=r"(r[0]), "=r"(r[1]) : "r"(addr));
}
__device__ __forceinline__ void mma_bf16(float* c, const uint32_t* a, const uint32_t* b) {
    asm volatile(
        "mma.sync.aligned.m16n8k16.row.col.f32.bf16.bf16.f32 "
        "{%0,%1,%2,%3}, {%4,%5,%6,%7}, {%8,%9}, {%0,%1,%2,%3};"
        : "+f"(c[0]), "+f"(c[1]), "+f"(c[2]), "+f"(c[3])
        : "r"(a[0]), "r"(a[1]), "r"(a[2]), "r"(a[3]), "r"(b[0]), "r"(b[1]));
}
// float -> (hi bf16, lo bf16) with lo = residual
__device__ __forceinline__ void split1(float v, uint16_t& h, uint16_t& l) {
    __nv_bfloat16 hb = __float2bfloat16_rn(v);
    float r = v - __bfloat162float(hb);
    __nv_bfloat16 lb = __float2bfloat16_rn(r);
    h = *reinterpret_cast<uint16_t*>(&hb);
    l = *reinterpret_cast<uint16_t*>(&lb);
}
__device__ __forceinline__ void pack2(float a, float b, uint32_t& hi, uint32_t& lo) {
    uint16_t ha, la, hb, lb;
    split1(a, ha, la);
    split1(b, hb, lb);
    hi = (uint32_t)ha | ((uint32_t)hb << 16);
    lo = (uint32_t)la | ((uint32_t)lb << 16);
}

// ======================= split-bf16 HMMA GEMM ===============================
// C[m,n] = sum_k A[m,k]*B'[k,n] (+bias[n]) (+res[m,n]); fp32 in/out.
// BNT=1: B is (N,K) row-major (torch Linear weight). BNT=0: B is (K,N) row-major.
// CTA tile 128x128, BK=32, 256 threads, 8 warps of 64x32. Dims must divide.
#define SROWB 80          // smem bytes per row (40 bf16, pad breaks ldsm conflicts)
#define OFF_AH 0
#define OFF_AL (OFF_AH + 128 * SROWB)
#define OFF_BH (OFF_AL + 128 * SROWB)
#define OFF_BL (OFF_BH + 128 * SROWB)
#define GEMM_SMEM (OFF_BL + 128 * SROWB)   // 40960 B

template<int BNT, int BIAS, int RES>
__global__ __launch_bounds__(256)
void hgemm(const float* __restrict__ A, int lda,
           const float* __restrict__ B, int ldb,
           const float* __restrict__ bias,
           const float* __restrict__ res, int ldr,
           float* __restrict__ C, int ldc, int K)
{
    __shared__ char smem[GEMM_SMEM];
    const uint32_t sbase = smem_u32(smem);

    const int tid  = threadIdx.x;
    const int lane = tid & 31;
    const int wid  = tid >> 5;
    const int wm   = wid >> 2;       // 0..1  (M warp)
    const int wn   = wid & 3;        // 0..3  (N warp)
    const int bm   = blockIdx.y * 128;
    const int bn   = blockIdx.x * 128;

    // ---- loader assignments ----
    // A (and B when BNT=1): 4 passes; row = p*32 + (tid>>3), float4 at col (tid&7)*4
    const int arow_l = tid >> 3;     // 0..31
    const int ac4    = tid & 7;      // 0..7
    // B when BNT=0: n = tid&127 (warp-coalesced over n), khalf = tid>>7
    const int bn_l   = tid & 127;
    const int bkh    = tid >> 7;

    float4 astg[4];
    float4 bstg[4];          // BNT=1 staging
    float  bstgT[16];        // BNT=0 staging

    float acc[4][4][4];
#pragma unroll
    for (int i = 0; i < 4; i++)
#pragma unroll
        for (int j = 0; j < 4; j++)
#pragma unroll
            for (int t = 0; t < 4; t++) acc[i][j][t] = 0.f;

    // ldmatrix per-thread base offsets
    const uint32_t a_off = sbase + (uint32_t)((wm * 64 + (lane & 15)) * SROWB + (lane >> 4) * 16);
    const uint32_t b_off = sbase + (uint32_t)((wn * 32 + (lane & 7)) * SROWB + ((lane >> 3) & 1) * 16);

    const int nchunks = K / 32;

    // ---- prologue: load chunk 0 into regs ----
    {
#pragma unroll
        for (int p = 0; p < 4; p++)
            astg[p] = *(const float4*)(A + (size_t)(bm + p * 32 + arow_l) * lda + ac4 * 4);
        if (BNT) {
#pragma unroll
            for (int p = 0; p < 4; p++)
                bstg[p] = *(const float4*)(B + (size_t)(bn + p * 32 + arow_l) * ldb + ac4 * 4);
        } else {
#pragma unroll
            for (int i = 0; i < 16; i++)
                bstgT[i] = B[(size_t)(bkh * 16 + i) * ldb + bn + bn_l];
        }
    }

    for (int c = 0; c < nchunks; c++) {
        // ---- convert staged regs -> smem (hi/lo bf16) ----
#pragma unroll
        for (int p = 0; p < 4; p++) {
            uint32_t h0, l0, h1, l1;
            pack2(astg[p].x, astg[p].y, h0, l0);
            pack2(astg[p].z, astg[p].w, h1, l1);
            char* dst = smem + (p * 32 + arow_l) * SROWB + ac4 * 8;
            *(uint2*)(dst + OFF_AH) = make_uint2(h0, h1);
            *(uint2*)(dst + OFF_AL) = make_uint2(l0, l1);
        }
        if (BNT) {
#pragma unroll
            for (int p = 0; p < 4; p++) {
                uint32_t h0, l0, h1, l1;
                pack2(bstg[p].x, bstg[p].y, h0, l0);
                pack2(bstg[p].z, bstg[p].w, h1, l1);
                char* dst = smem + (p * 32 + arow_l) * SROWB + ac4 * 8;
                *(uint2*)(dst + OFF_BH) = make_uint2(h0, h1);
                *(uint2*)(dst + OFF_BL) = make_uint2(l0, l1);
            }
        } else {
#pragma unroll
            for (int j = 0; j < 8; j++) {
                uint32_t h, l;
                pack2(bstgT[2 * j], bstgT[2 * j + 1], h, l);
                char* dst = smem + bn_l * SROWB + bkh * 32 + j * 4;
                *(uint32_t*)(dst + OFF_BH) = h;
                *(uint32_t*)(dst + OFF_BL) = l;
            }
        }
        __syncthreads();

        // ---- prefetch next chunk into regs (overlaps MMA below) ----
        if (c + 1 < nchunks) {
            const int k0 = (c + 1) * 32;
#pragma unroll
            for (int p = 0; p < 4; p++)
                astg[p] = *(const float4*)(A + (size_t)(bm + p * 32 + arow_l) * lda + k0 + ac4 * 4);
            if (BNT) {
#pragma unroll
                for (int p = 0; p < 4; p++)
                    bstg[p] = *(const float4*)(B + (size_t)(bn + p * 32 + arow_l) * ldb + k0 + ac4 * 4);
            } else {
#pragma unroll
                for (int i = 0; i < 16; i++)
                    bstgT[i] = B[(size_t)(k0 + bkh * 16 + i) * ldb + bn + bn_l];
            }
        }

        // ---- MMA over this chunk ----
#pragma unroll
        for (int ks = 0; ks < 2; ks++) {
            uint32_t ah[4][4], al[4][4], bh[4][2], bl[4][2];
#pragma unroll
            for (int mt = 0; mt < 4; mt++) {
                uint32_t ad = a_off + (uint32_t)(mt * 16 * SROWB + ks * 32);
                ldsm_x4(ah[mt], ad + OFF_AH);
                ldsm_x4(al[mt], ad + OFF_AL);
            }
#pragma unroll
            for (int nt = 0; nt < 4; nt++) {
                uint32_t bd = b_off + (uint32_t)(nt * 8 * SROWB + ks * 32);
                ldsm_x2(bh[nt], bd + OFF_BH);
                ldsm_x2(bl[nt], bd + OFF_BL);
            }
#pragma unroll
            for (int mt = 0; mt < 4; mt++)
#pragma unroll
                for (int nt = 0; nt < 4; nt++) {
                    mma_bf16(acc[mt][nt], ah[mt], bh[nt]);
                    mma_bf16(acc[mt][nt], ah[mt], bl[nt]);
                    mma_bf16(acc[mt][nt], al[mt], bh[nt]);
                }
        }
        __syncthreads();
    }

    // ---- epilogue: fragment layout -> C (+bias +res) ----
#pragma unroll
    for (int mt = 0; mt < 4; mt++) {
#pragma unroll
        for (int nt = 0; nt < 4; nt++) {
            const int m0 = bm + wm * 64 + mt * 16 + (lane >> 2);
            const int n0 = bn + wn * 32 + nt * 8 + 2 * (lane & 3);
            float2 v0 = make_float2(acc[mt][nt][0], acc[mt][nt][1]);
            float2 v1 = make_float2(acc[mt][nt][2], acc[mt][nt][3]);
            if (BIAS) {
                float2 bb = *(const float2*)(bias + n0);
                v0.x += bb.x; v0.y += bb.y;
                v1.x += bb.x; v1.y += bb.y;
            }
            if (RES) {
                float2 r0 = *(const float2*)(res + (size_t)m0 * ldr + n0);
                float2 r1 = *(const float2*)(res + (size_t)(m0 + 8) * ldr + n0);
                v0.x += r0.x; v0.y += r0.y;
                v1.x += r1.x; v1.y += r1.y;
            }
            *(float2*)(C + (size_t)m0 * ldc + n0) = v0;
            *(float2*)(C + (size_t)(m0 + 8) * ldc + n0) = v1;
        }
    }
}

// ---------------- flash attention: 2 threads per q-row ----------------------
// grid (SEQ/128, NHEAD, BATCH), 256 threads. Thread pair (2r, 2r+1) owns q-row r;
// each half handles 32 of the 64 dims; shfl.bfly(1) merges the dot product.
__global__ __launch_bounds__(256)
void flash_kernel(const float* __restrict__ Q, const float* __restrict__ Kp,
                  const float* __restrict__ V, float* __restrict__ O)
{
    __shared__ float Ks[64][64];
    __shared__ float Vs[64][64];

    const int tid  = threadIdx.x;
    const int half = tid & 1;
    const int row  = tid >> 1;
    const int h = blockIdx.y;
    const int b = blockIdx.z;
    const int qrow = blockIdx.x * 128 + row;
    const int d0 = half * 32;

    const float* qptr = Q + ((size_t)(b * SEQ + qrow)) * E_DIM + h * HDIM + d0;
    float qr[32];
#pragma unroll
    for (int d = 0; d < 32; d += 4) {
        float4 t = *(const float4*)(qptr + d);
        qr[d + 0] = t.x * 0.125f;
        qr[d + 1] = t.y * 0.125f;
        qr[d + 2] = t.z * 0.125f;
        qr[d + 3] = t.w * 0.125f;
    }

    float acc[32];
#pragma unroll
    for (int d = 0; d < 32; d++) acc[d] = 0.f;
    float mi = -1e30f, li = 0.f;

    const float* kbase = Kp + ((size_t)b * SEQ) * E_DIM + h * HDIM;
    const float* vbase = V + ((size_t)b * SEQ) * (3 * E_DIM) + h * HDIM;

    for (int j0 = 0; j0 < SEQ; j0 += 64) {
        __syncthreads();
#pragma unroll
        for (int it = 0; it < 4; it++) {
            int idx4 = tid + it * 256;          // 0..1023
            int r = idx4 >> 4;
            int c4 = idx4 & 15;
            *(float4*)&Ks[r][c4 * 4] =
                *(const float4*)(kbase + (size_t)(j0 + r) * E_DIM + c4 * 4);
            *(float4*)&Vs[r][c4 * 4] =
                *(const float4*)(vbase + (size_t)(j0 + r) * (3 * E_DIM) + c4 * 4);
        }
        __syncthreads();

#pragma unroll 4
        for (int kk = 0; kk < 64; kk++) {
            const float4* krow = (const float4*)&Ks[kk][d0];
            float s = 0.f;
#pragma unroll
            for (int d4 = 0; d4 < 8; d4++) {
                float4 kv = krow[d4];
                s = fmaf(qr[4 * d4 + 0], kv.x, s);
                s = fmaf(qr[4 * d4 + 1], kv.y, s);
                s = fmaf(qr[4 * d4 + 2], kv.z, s);
                s = fmaf(qr[4 * d4 + 3], kv.w, s);
            }
            s += __shfl_xor_sync(0xffffffffu, s, 1);
            if (s > mi) {
                float cc = __expf(mi - s);
                mi = s;
                li *= cc;
#pragma unroll
                for (int d = 0; d < 32; d++) acc[d] *= cc;
            }
            float p = __expf(s - mi);
            li += p;
            const float4* vrow = (const float4*)&Vs[kk][d0];
#pragma unroll
            for (int d4 = 0; d4 < 8; d4++) {
                float4 vv = vrow[d4];
                acc[4 * d4 + 0] = fmaf(p, vv.x, acc[4 * d4 + 0]);
                acc[4 * d4 + 1] = fmaf(p, vv.y, acc[4 * d4 + 1]);
                acc[4 * d4 + 2] = fmaf(p, vv.z, acc[4 * d4 + 2]);
                acc[4 * d4 + 3] = fmaf(p, vv.w, acc[4 * d4 + 3]);
            }
        }
    }

    float inv = 1.f / li;
    float* optr = O + ((size_t)(b * SEQ + qrow)) * E_DIM + h * HDIM + d0;
#pragma unroll
    for (int d = 0; d < 32; d += 4) {
        float4 t;
        t.x = acc[d + 0] * inv;
        t.y = acc[d + 1] * inv;
        t.z = acc[d + 2] * inv;
        t.w = acc[d + 3] * inv;
        *(float4*)(optr + d) = t;
    }
}

// ---------------- launcher ---------------------------------------------------
extern "C" void kernel_launch(void* const* d_in, const int* in_sizes, int n_in,
                              void* d_out, int out_size)
{
    (void)in_sizes; (void)n_in; (void)out_size;
    const float* x    = (const float*)d_in[0];
    const float* rot  = (const float*)d_in[1];
    const float* ent  = (const float*)d_in[2];
    const float* qkvw = (const float*)d_in[3];
    const float* qkvb = (const float*)d_in[4];
    const float* outw = (const float*)d_in[5];
    const float* outb = (const float*)d_in[6];
    float* out = (float*)d_out;

    float *qkv, *q, *k, *o;
    cudaGetSymbolAddress((void**)&qkv, g_qkv);
    cudaGetSymbolAddress((void**)&q,   g_q);
    cudaGetSymbolAddress((void**)&k,   g_k);
    cudaGetSymbolAddress((void**)&o,   g_o);

    // 1) qkv = x @ qkv_w^T + qkv_b   (4096 x 3072 x 1024, NT)
    hgemm<1, 1, 0><<<dim3(3 * E_DIM / 128, MROWS / 128), 256>>>(
        x, E_DIM, qkvw, E_DIM, qkvb, nullptr, 0, qkv, 3 * E_DIM, E_DIM);

    // 2) q' = qkv[:, 0:1024] @ rotation   (NN)
    hgemm<0, 0, 0><<<dim3(E_DIM / 128, MROWS / 128), 256>>>(
        qkv, 3 * E_DIM, rot, E_DIM, nullptr, nullptr, 0, q, E_DIM, E_DIM);

    // 3) k' = qkv[:, 1024:2048] @ entangle (NN)
    hgemm<0, 0, 0><<<dim3(E_DIM / 128, MROWS / 128), 256>>>(
        qkv + E_DIM, 3 * E_DIM, ent, E_DIM, nullptr, nullptr, 0, k, E_DIM, E_DIM);

    // 4) attention: O = softmax(q' k'^T / 8) @ v
    flash_kernel<<<dim3(SEQ / 128, NHEAD, BATCH), 256>>>(
        q, k, qkv + 2 * E_DIM, o);

    // 5) out = O @ out_w^T + out_b + x    (NT + bias + residual)
    hgemm<1, 1, 1><<<dim3(E_DIM / 128, MROWS / 128), 256>>>(
        o, E_DIM, outw, E_DIM, outb, x, E_DIM, out, E_DIM, E_DIM);
}

// round 5
// speedup vs baseline: 2.5357x; 2.1355x over previous
#include <cuda_runtime.h>
#include <cuda_bf16.h>
#include <cstdint>
#include <math.h>

#define E_DIM 1024
#define NHEAD 16
#define HDIM  64
#define BATCH 2
#define SEQ   2048
#define MROWS (BATCH * SEQ)   // 4096

// ---------------- scratch (static device globals: allocation-guard safe) ----
__device__ float g_qkv[(size_t)MROWS * 3 * E_DIM];
__device__ float g_q  [(size_t)MROWS * E_DIM];
__device__ float g_k  [(size_t)MROWS * E_DIM];
__device__ float g_o  [(size_t)MROWS * E_DIM];

// ======================= mma.sync helpers ===================================
__device__ __forceinline__ uint32_t smem_u32(const void* p) {
    uint32_t a;
    asm("{ .reg .u64 t; cvta.to.shared.u64 t, %1; cvt.u32.u64 %0, t; }" : "=r"(a) : "l"(p));
    return a;
}
__device__ __forceinline__ void ldsm_x4(uint32_t* r, uint32_t addr) {
    asm volatile("ldmatrix.sync.aligned.m8n8.x4.shared.b16 {%0,%1,%2,%3}, [%4];"
                 : "=r"(r[0]), "=r"(r[1]), "=r"(r[2]), "=r"(r[3]) : "r"(addr));
}
__device__ __forceinline__ void ldsm_x2(uint32_t* r, uint32_t addr) {
    asm volatile("ldmatrix.sync.aligned.m8n8.x2.shared.b16 {%0,%1}, [%2];"
                 : "=r"(r[0]), "=r"(r[1]) : "r"(addr));
}
__device__ __forceinline__ void mma_bf16(float* c, const uint32_t* a, const uint32_t* b) {
    asm volatile(
        "mma.sync.aligned.m16n8k16.row.col.f32.bf16.bf16.f32 "
        "{%0,%1,%2,%3}, {%4,%5,%6,%7}, {%8,%9}, {%0,%1,%2,%3};"
        : "+f"(c[0]), "+f"(c[1]), "+f"(c[2]), "+f"(c[3])
        : "r"(a[0]), "r"(a[1]), "r"(a[2]), "r"(a[3]), "r"(b[0]), "r"(b[1]));
}
__device__ __forceinline__ void split1(float v, uint16_t& h, uint16_t& l) {
    __nv_bfloat16 hb = __float2bfloat16_rn(v);
    float r = v - __bfloat162float(hb);
    __nv_bfloat16 lb = __float2bfloat16_rn(r);
    h = *reinterpret_cast<uint16_t*>(&hb);
    l = *reinterpret_cast<uint16_t*>(&lb);
}
__device__ __forceinline__ void pack2(float a, float b, uint32_t& hi, uint32_t& lo) {
    uint16_t ha, la, hb, lb;
    split1(a, ha, la);
    split1(b, hb, lb);
    hi = (uint32_t)ha | ((uint32_t)hb << 16);
    lo = (uint32_t)la | ((uint32_t)lb << 16);
}

// ======================= split-bf16 HMMA GEMM (unchanged, passing) ==========
#define SROWB 80
#define OFF_AH 0
#define OFF_AL (OFF_AH + 128 * SROWB)
#define OFF_BH (OFF_AL + 128 * SROWB)
#define OFF_BL (OFF_BH + 128 * SROWB)
#define GEMM_SMEM (OFF_BL + 128 * SROWB)

template<int BNT, int BIAS, int RES>
__global__ __launch_bounds__(256)
void hgemm(const float* __restrict__ A, int lda,
           const float* __restrict__ B, int ldb,
           const float* __restrict__ bias,
           const float* __restrict__ res, int ldr,
           float* __restrict__ C, int ldc, int K)
{
    __shared__ char smem[GEMM_SMEM];
    const uint32_t sbase = smem_u32(smem);

    const int tid  = threadIdx.x;
    const int lane = tid & 31;
    const int wid  = tid >> 5;
    const int wm   = wid >> 2;
    const int wn   = wid & 3;
    const int bm   = blockIdx.y * 128;
    const int bn   = blockIdx.x * 128;

    const int arow_l = tid >> 3;
    const int ac4    = tid & 7;
    const int bn_l   = tid & 127;
    const int bkh    = tid >> 7;

    float4 astg[4];
    float4 bstg[4];
    float  bstgT[16];

    float acc[4][4][4];
#pragma unroll
    for (int i = 0; i < 4; i++)
#pragma unroll
        for (int j = 0; j < 4; j++)
#pragma unroll
            for (int t = 0; t < 4; t++) acc[i][j][t] = 0.f;

    const uint32_t a_off = sbase + (uint32_t)((wm * 64 + (lane & 15)) * SROWB + (lane >> 4) * 16);
    const uint32_t b_off = sbase + (uint32_t)((wn * 32 + (lane & 7)) * SROWB + ((lane >> 3) & 1) * 16);

    const int nchunks = K / 32;

    {
#pragma unroll
        for (int p = 0; p < 4; p++)
            astg[p] = *(const float4*)(A + (size_t)(bm + p * 32 + arow_l) * lda + ac4 * 4);
        if (BNT) {
#pragma unroll
            for (int p = 0; p < 4; p++)
                bstg[p] = *(const float4*)(B + (size_t)(bn + p * 32 + arow_l) * ldb + ac4 * 4);
        } else {
#pragma unroll
            for (int i = 0; i < 16; i++)
                bstgT[i] = B[(size_t)(bkh * 16 + i) * ldb + bn + bn_l];
        }
    }

    for (int c = 0; c < nchunks; c++) {
#pragma unroll
        for (int p = 0; p < 4; p++) {
            uint32_t h0, l0, h1, l1;
            pack2(astg[p].x, astg[p].y, h0, l0);
            pack2(astg[p].z, astg[p].w, h1, l1);
            char* dst = smem + (p * 32 + arow_l) * SROWB + ac4 * 8;
            *(uint2*)(dst + OFF_AH) = make_uint2(h0, h1);
            *(uint2*)(dst + OFF_AL) = make_uint2(l0, l1);
        }
        if (BNT) {
#pragma unroll
            for (int p = 0; p < 4; p++) {
                uint32_t h0, l0, h1, l1;
                pack2(bstg[p].x, bstg[p].y, h0, l0);
                pack2(bstg[p].z, bstg[p].w, h1, l1);
                char* dst = smem + (p * 32 + arow_l) * SROWB + ac4 * 8;
                *(uint2*)(dst + OFF_BH) = make_uint2(h0, h1);
                *(uint2*)(dst + OFF_BL) = make_uint2(l0, l1);
            }
        } else {
#pragma unroll
            for (int j = 0; j < 8; j++) {
                uint32_t h, l;
                pack2(bstgT[2 * j], bstgT[2 * j + 1], h, l);
                char* dst = smem + bn_l * SROWB + bkh * 32 + j * 4;
                *(uint32_t*)(dst + OFF_BH) = h;
                *(uint32_t*)(dst + OFF_BL) = l;
            }
        }
        __syncthreads();

        if (c + 1 < nchunks) {
            const int k0 = (c + 1) * 32;
#pragma unroll
            for (int p = 0; p < 4; p++)
                astg[p] = *(const float4*)(A + (size_t)(bm + p * 32 + arow_l) * lda + k0 + ac4 * 4);
            if (BNT) {
#pragma unroll
                for (int p = 0; p < 4; p++)
                    bstg[p] = *(const float4*)(B + (size_t)(bn + p * 32 + arow_l) * ldb + k0 + ac4 * 4);
            } else {
#pragma unroll
                for (int i = 0; i < 16; i++)
                    bstgT[i] = B[(size_t)(k0 + bkh * 16 + i) * ldb + bn + bn_l];
            }
        }

#pragma unroll
        for (int ks = 0; ks < 2; ks++) {
            uint32_t ah[4][4], al[4][4], bh[4][2], bl[4][2];
#pragma unroll
            for (int mt = 0; mt < 4; mt++) {
                uint32_t ad = a_off + (uint32_t)(mt * 16 * SROWB + ks * 32);
                ldsm_x4(ah[mt], ad + OFF_AH);
                ldsm_x4(al[mt], ad + OFF_AL);
            }
#pragma unroll
            for (int nt = 0; nt < 4; nt++) {
                uint32_t bd = b_off + (uint32_t)(nt * 8 * SROWB + ks * 32);
                ldsm_x2(bh[nt], bd + OFF_BH);
                ldsm_x2(bl[nt], bd + OFF_BL);
            }
#pragma unroll
            for (int mt = 0; mt < 4; mt++)
#pragma unroll
                for (int nt = 0; nt < 4; nt++) {
                    mma_bf16(acc[mt][nt], ah[mt], bh[nt]);
                    mma_bf16(acc[mt][nt], ah[mt], bl[nt]);
                    mma_bf16(acc[mt][nt], al[mt], bh[nt]);
                }
        }
        __syncthreads();
    }

#pragma unroll
    for (int mt = 0; mt < 4; mt++) {
#pragma unroll
        for (int nt = 0; nt < 4; nt++) {
            const int m0 = bm + wm * 64 + mt * 16 + (lane >> 2);
            const int n0 = bn + wn * 32 + nt * 8 + 2 * (lane & 3);
            float2 v0 = make_float2(acc[mt][nt][0], acc[mt][nt][1]);
            float2 v1 = make_float2(acc[mt][nt][2], acc[mt][nt][3]);
            if (BIAS) {
                float2 bb = *(const float2*)(bias + n0);
                v0.x += bb.x; v0.y += bb.y;
                v1.x += bb.x; v1.y += bb.y;
            }
            if (RES) {
                float2 r0 = *(const float2*)(res + (size_t)m0 * ldr + n0);
                float2 r1 = *(const float2*)(res + (size_t)(m0 + 8) * ldr + n0);
                v0.x += r0.x; v0.y += r0.y;
                v1.x += r1.x; v1.y += r1.y;
            }
            *(float2*)(C + (size_t)m0 * ldc + n0) = v0;
            *(float2*)(C + (size_t)(m0 + 8) * ldc + n0) = v1;
        }
    }
}

// ======================= HMMA flash attention ================================
// grid (SEQ/64, NHEAD, BATCH), 128 threads (4 warps x 16 q-rows).
// S = Q K^T via split-bf16 mma (Q row-major A; K (keys,dims) = (N,K) B).
// Online softmax in fp32 S fragments; P fragments re-pack directly as A of PV.
// V stored transposed (dim-major) in smem so PV B is the same (N,K) pattern.
#define TROWB 144                       // 64 bf16 = 128B + 16B pad
#define FKH 0
#define FKL (FKH + 64 * TROWB)
#define FVH (FKL + 64 * TROWB)
#define FVL (FVH + 64 * TROWB)
#define FLASH_SMEM (FVL + 64 * TROWB)   // 36864 B

__global__ __launch_bounds__(128)
void flash_mma(const float* __restrict__ Q, const float* __restrict__ Kp,
               const float* __restrict__ V, float* __restrict__ O)
{
    __shared__ char smem[FLASH_SMEM];
    const uint32_t sbase = smem_u32(smem);

    const int tid  = threadIdx.x;
    const int lane = tid & 31;
    const int w    = tid >> 5;          // warp 0..3 -> q rows 16w..16w+15
    const int h = blockIdx.y;
    const int b = blockIdx.z;
    const int bq = blockIdx.x * 64;

    const float* qbase = Q  + ((size_t)(b * SEQ + bq)) * E_DIM + h * HDIM;
    const float* kbase = Kp + ((size_t)b * SEQ) * E_DIM + h * HDIM;
    const float* vbase = V  + ((size_t)b * SEQ) * (3 * E_DIM) + h * HDIM;

    // ---- stage Q (scaled by 1/8) into smem (K region), ldsm into fragments --
#pragma unroll
    for (int it = 0; it < 8; it++) {
        int idx = tid + it * 128;       // 0..1023
        int r  = idx >> 4;              // q row 0..63
        int c4 = idx & 15;
        float4 qv = *(const float4*)(qbase + (size_t)r * E_DIM + c4 * 4);
        uint32_t h0, l0, h1, l1;
        pack2(qv.x * 0.125f, qv.y * 0.125f, h0, l0);
        pack2(qv.z * 0.125f, qv.w * 0.125f, h1, l1);
        char* dst = smem + r * TROWB + c4 * 8;
        *(uint2*)(dst + FKH) = make_uint2(h0, h1);
        *(uint2*)(dst + FKL) = make_uint2(l0, l1);
    }
    __syncthreads();

    uint32_t qh[4][4], ql[4][4];
    {
        const uint32_t a_off = sbase + (uint32_t)((w * 16 + (lane & 15)) * TROWB + (lane >> 4) * 16);
#pragma unroll
        for (int ks = 0; ks < 4; ks++) {
            ldsm_x4(qh[ks], a_off + FKH + ks * 32);
            ldsm_x4(ql[ks], a_off + FKL + ks * 32);
        }
    }

    float o[8][4];
#pragma unroll
    for (int nt = 0; nt < 8; nt++)
#pragma unroll
        for (int t = 0; t < 4; t++) o[nt][t] = 0.f;
    float mrow[2] = {-1e30f, -1e30f};
    float lrow[2] = {0.f, 0.f};

    const uint32_t b_off = sbase + (uint32_t)(((lane & 7)) * TROWB + ((lane >> 3) & 1) * 16);

    for (int j0 = 0; j0 < SEQ; j0 += 64) {
        __syncthreads();  // done reading previous tile (and Q staging on iter 0)
        // ---- load K tile (row-major keys x dims) + V tile (TRANSPOSED) ------
#pragma unroll
        for (int it = 0; it < 8; it++) {
            int idx = tid + it * 128;
            int r  = idx >> 4;          // key 0..63
            int c4 = idx & 15;
            float4 kv = *(const float4*)(kbase + (size_t)(j0 + r) * E_DIM + c4 * 4);
            uint32_t h0, l0, h1, l1;
            pack2(kv.x, kv.y, h0, l0);
            pack2(kv.z, kv.w, h1, l1);
            char* kd = smem + r * TROWB + c4 * 8;
            *(uint2*)(kd + FKH) = make_uint2(h0, h1);
            *(uint2*)(kd + FKL) = make_uint2(l0, l1);

            float4 vv = *(const float4*)(vbase + (size_t)(j0 + r) * (3 * E_DIM) + c4 * 4);
            float vf[4] = {vv.x, vv.y, vv.z, vv.w};
#pragma unroll
            for (int j = 0; j < 4; j++) {
                uint16_t vh, vl;
                split1(vf[j], vh, vl);
                int d = c4 * 4 + j;
                *(uint16_t*)(smem + FVH + d * TROWB + r * 2) = vh;
                *(uint16_t*)(smem + FVL + d * TROWB + r * 2) = vl;
            }
        }
        __syncthreads();

        // ---- S = Q K^T (fp32 accum, 3-term compensated) --------------------
        float s[8][4];
#pragma unroll
        for (int nt = 0; nt < 8; nt++)
#pragma unroll
            for (int t = 0; t < 4; t++) s[nt][t] = 0.f;
#pragma unroll
        for (int ks = 0; ks < 4; ks++) {
#pragma unroll
            for (int nt = 0; nt < 8; nt++) {
                uint32_t bd = b_off + (uint32_t)(nt * 8 * TROWB + ks * 32);
                uint32_t bh[2], bl[2];
                ldsm_x2(bh, bd + FKH);
                ldsm_x2(bl, bd + FKL);
                mma_bf16(s[nt], qh[ks], bh);
                mma_bf16(s[nt], qh[ks], bl);
                mma_bf16(s[nt], ql[ks], bh);
            }
        }

        // ---- online softmax (rows r=0: regs 0,1 ; r=1: regs 2,3) -----------
#pragma unroll
        for (int r = 0; r < 2; r++) {
            const int off = 2 * r;
            float mx = s[0][off];
#pragma unroll
            for (int nt = 0; nt < 8; nt++) {
                mx = fmaxf(mx, s[nt][off]);
                mx = fmaxf(mx, s[nt][off + 1]);
            }
            mx = fmaxf(mx, __shfl_xor_sync(0xffffffffu, mx, 1));
            mx = fmaxf(mx, __shfl_xor_sync(0xffffffffu, mx, 2));
            float mnew = fmaxf(mrow[r], mx);
            float sc = __expf(mrow[r] - mnew);
            mrow[r] = mnew;
            float sum = 0.f;
#pragma unroll
            for (int nt = 0; nt < 8; nt++) {
                s[nt][off]     = __expf(s[nt][off]     - mnew);
                s[nt][off + 1] = __expf(s[nt][off + 1] - mnew);
                sum += s[nt][off] + s[nt][off + 1];
            }
            sum += __shfl_xor_sync(0xffffffffu, sum, 1);
            sum += __shfl_xor_sync(0xffffffffu, sum, 2);
            lrow[r] = lrow[r] * sc + sum;
#pragma unroll
            for (int nt = 0; nt < 8; nt++) {
                o[nt][off]     *= sc;
                o[nt][off + 1] *= sc;
            }
        }

        // ---- O += P V  (P from s fragments, split hi/lo; V transposed) ------
#pragma unroll
        for (int ks = 0; ks < 4; ks++) {
            uint32_t pa[4], pl[4];
            pack2(s[2 * ks][0],     s[2 * ks][1],     pa[0], pl[0]);
            pack2(s[2 * ks][2],     s[2 * ks][3],     pa[1], pl[1]);
            pack2(s[2 * ks + 1][0], s[2 * ks + 1][1], pa[2], pl[2]);
            pack2(s[2 * ks + 1][2], s[2 * ks + 1][3], pa[3], pl[3]);
#pragma unroll
            for (int nt = 0; nt < 8; nt++) {
                uint32_t bd = b_off + (uint32_t)(nt * 8 * TROWB + ks * 32);
                uint32_t bh[2], bl[2];
                ldsm_x2(bh, bd + FVH);
                ldsm_x2(bl, bd + FVL);
                mma_bf16(o[nt], pa, bh);
                mma_bf16(o[nt], pa, bl);
                mma_bf16(o[nt], pl, bh);
            }
        }
    }

    // ---- epilogue -----------------------------------------------------------
    const float inv0 = 1.f / lrow[0];
    const float inv1 = 1.f / lrow[1];
    const int m0 = b * SEQ + bq + w * 16 + (lane >> 2);
#pragma unroll
    for (int nt = 0; nt < 8; nt++) {
        const int n = h * HDIM + nt * 8 + 2 * (lane & 3);
        *(float2*)(O + (size_t)m0 * E_DIM + n) =
            make_float2(o[nt][0] * inv0, o[nt][1] * inv0);
        *(float2*)(O + (size_t)(m0 + 8) * E_DIM + n) =
            make_float2(o[nt][2] * inv1, o[nt][3] * inv1);
    }
}

// ---------------- launcher ---------------------------------------------------
extern "C" void kernel_launch(void* const* d_in, const int* in_sizes, int n_in,
                              void* d_out, int out_size)
{
    (void)in_sizes; (void)n_in; (void)out_size;
    const float* x    = (const float*)d_in[0];
    const float* rot  = (const float*)d_in[1];
    const float* ent  = (const float*)d_in[2];
    const float* qkvw = (const float*)d_in[3];
    const float* qkvb = (const float*)d_in[4];
    const float* outw = (const float*)d_in[5];
    const float* outb = (const float*)d_in[6];
    float* out = (float*)d_out;

    float *qkv, *q, *k, *o;
    cudaGetSymbolAddress((void**)&qkv, g_qkv);
    cudaGetSymbolAddress((void**)&q,   g_q);
    cudaGetSymbolAddress((void**)&k,   g_k);
    cudaGetSymbolAddress((void**)&o,   g_o);

    // 1) qkv = x @ qkv_w^T + qkv_b   (4096 x 3072 x 1024, NT)
    hgemm<1, 1, 0><<<dim3(3 * E_DIM / 128, MROWS / 128), 256>>>(
        x, E_DIM, qkvw, E_DIM, qkvb, nullptr, 0, qkv, 3 * E_DIM, E_DIM);

    // 2) q' = qkv[:, 0:1024] @ rotation   (NN)
    hgemm<0, 0, 0><<<dim3(E_DIM / 128, MROWS / 128), 256>>>(
        qkv, 3 * E_DIM, rot, E_DIM, nullptr, nullptr, 0, q, E_DIM, E_DIM);

    // 3) k' = qkv[:, 1024:2048] @ entangle (NN)
    hgemm<0, 0, 0><<<dim3(E_DIM / 128, MROWS / 128), 256>>>(
        qkv + E_DIM, 3 * E_DIM, ent, E_DIM, nullptr, nullptr, 0, k, E_DIM, E_DIM);

    // 4) attention (HMMA): O = softmax(q' k'^T / 8) @ v
    flash_mma<<<dim3(SEQ / 64, NHEAD, BATCH), 128>>>(
        q, k, qkv + 2 * E_DIM, o);

    // 5) out = O @ out_w^T + out_b + x    (NT + bias + residual)
    hgemm<1, 1, 1><<<dim3(E_DIM / 128, MROWS / 128), 256>>>(
        o, E_DIM, outw, E_DIM, outb, x, E_DIM, out, E_DIM, E_DIM);
}

// round 6
// speedup vs baseline: 2.9857x; 1.1775x over previous
#include <cuda_runtime.h>
#include <cuda_bf16.h>
#include <cstdint>
#include <math.h>

#define E_DIM 1024
#define NHEAD 16
#define HDIM  64
#define BATCH 2
#define SEQ   2048
#define MROWS (BATCH * SEQ)   // 4096

// ---------------- scratch (static device globals: allocation-guard safe) ----
__device__ float g_qkv[(size_t)MROWS * 3 * E_DIM];
__device__ float g_q  [(size_t)MROWS * E_DIM];
__device__ float g_k  [(size_t)MROWS * E_DIM];
__device__ float g_o  [(size_t)MROWS * E_DIM];

// ======================= mma.sync helpers ===================================
__device__ __forceinline__ uint32_t smem_u32(const void* p) {
    uint32_t a;
    asm("{ .reg .u64 t; cvta.to.shared.u64 t, %1; cvt.u32.u64 %0, t; }" : "=r"(a) : "l"(p));
    return a;
}
__device__ __forceinline__ void ldsm_x4(uint32_t* r, uint32_t addr) {
    asm volatile("ldmatrix.sync.aligned.m8n8.x4.shared.b16 {%0,%1,%2,%3}, [%4];"
                 : "=r"(r[0]), "=r"(r[1]), "=r"(r[2]), "=r"(r[3]) : "r"(addr));
}
__device__ __forceinline__ void ldsm_x4t(uint32_t* r, uint32_t addr) {
    asm volatile("ldmatrix.sync.aligned.m8n8.x4.trans.shared.b16 {%0,%1,%2,%3}, [%4];"
                 : "=r"(r[0]), "=r"(r[1]), "=r"(r[2]), "=r"(r[3]) : "r"(addr));
}
__device__ __forceinline__ void ldsm_x2(uint32_t* r, uint32_t addr) {
    asm volatile("ldmatrix.sync.aligned.m8n8.x2.shared.b16 {%0,%1}, [%2];"
                 : "=r"(r[0]), "=r"(r[1]) : "r"(addr));
}
__device__ __forceinline__ void mma_bf16(float* c, const uint32_t* a, const uint32_t* b) {
    asm volatile(
        "mma.sync.aligned.m16n8k16.row.col.f32.bf16.bf16.f32 "
        "{%0,%1,%2,%3}, {%4,%5,%6,%7}, {%8,%9}, {%0,%1,%2,%3};"
        : "+f"(c[0]), "+f"(c[1]), "+f"(c[2]), "+f"(c[3])
        : "r"(a[0]), "r"(a[1]), "r"(a[2]), "r"(a[3]), "r"(b[0]), "r"(b[1]));
}
__device__ __forceinline__ void split1(float v, uint16_t& h, uint16_t& l) {
    __nv_bfloat16 hb = __float2bfloat16_rn(v);
    float r = v - __bfloat162float(hb);
    __nv_bfloat16 lb = __float2bfloat16_rn(r);
    h = *reinterpret_cast<uint16_t*>(&hb);
    l = *reinterpret_cast<uint16_t*>(&lb);
}
__device__ __forceinline__ void pack2(float a, float b, uint32_t& hi, uint32_t& lo) {
    uint16_t ha, la, hb, lb;
    split1(a, ha, la);
    split1(b, hb, lb);
    hi = (uint32_t)ha | ((uint32_t)hb << 16);
    lo = (uint32_t)la | ((uint32_t)lb << 16);
}

// ======================= split-bf16 HMMA GEMM (unchanged, passing) ==========
#define SROWB 80
#define OFF_AH 0
#define OFF_AL (OFF_AH + 128 * SROWB)
#define OFF_BH (OFF_AL + 128 * SROWB)
#define OFF_BL (OFF_BH + 128 * SROWB)
#define GEMM_SMEM (OFF_BL + 128 * SROWB)

template<int BNT, int BIAS, int RES>
__global__ __launch_bounds__(256)
void hgemm(const float* __restrict__ A, int lda,
           const float* __restrict__ B, int ldb,
           const float* __restrict__ bias,
           const float* __restrict__ res, int ldr,
           float* __restrict__ C, int ldc, int K)
{
    __shared__ char smem[GEMM_SMEM];
    const uint32_t sbase = smem_u32(smem);

    const int tid  = threadIdx.x;
    const int lane = tid & 31;
    const int wid  = tid >> 5;
    const int wm   = wid >> 2;
    const int wn   = wid & 3;
    const int bm   = blockIdx.y * 128;
    const int bn   = blockIdx.x * 128;

    const int arow_l = tid >> 3;
    const int ac4    = tid & 7;
    const int bn_l   = tid & 127;
    const int bkh    = tid >> 7;

    float4 astg[4];
    float4 bstg[4];
    float  bstgT[16];

    float acc[4][4][4];
#pragma unroll
    for (int i = 0; i < 4; i++)
#pragma unroll
        for (int j = 0; j < 4; j++)
#pragma unroll
            for (int t = 0; t < 4; t++) acc[i][j][t] = 0.f;

    const uint32_t a_off = sbase + (uint32_t)((wm * 64 + (lane & 15)) * SROWB + (lane >> 4) * 16);
    const uint32_t b_off = sbase + (uint32_t)((wn * 32 + (lane & 7)) * SROWB + ((lane >> 3) & 1) * 16);

    const int nchunks = K / 32;

    {
#pragma unroll
        for (int p = 0; p < 4; p++)
            astg[p] = *(const float4*)(A + (size_t)(bm + p * 32 + arow_l) * lda + ac4 * 4);
        if (BNT) {
#pragma unroll
            for (int p = 0; p < 4; p++)
                bstg[p] = *(const float4*)(B + (size_t)(bn + p * 32 + arow_l) * ldb + ac4 * 4);
        } else {
#pragma unroll
            for (int i = 0; i < 16; i++)
                bstgT[i] = B[(size_t)(bkh * 16 + i) * ldb + bn + bn_l];
        }
    }

    for (int c = 0; c < nchunks; c++) {
#pragma unroll
        for (int p = 0; p < 4; p++) {
            uint32_t h0, l0, h1, l1;
            pack2(astg[p].x, astg[p].y, h0, l0);
            pack2(astg[p].z, astg[p].w, h1, l1);
            char* dst = smem + (p * 32 + arow_l) * SROWB + ac4 * 8;
            *(uint2*)(dst + OFF_AH) = make_uint2(h0, h1);
            *(uint2*)(dst + OFF_AL) = make_uint2(l0, l1);
        }
        if (BNT) {
#pragma unroll
            for (int p = 0; p < 4; p++) {
                uint32_t h0, l0, h1, l1;
                pack2(bstg[p].x, bstg[p].y, h0, l0);
                pack2(bstg[p].z, bstg[p].w, h1, l1);
                char* dst = smem + (p * 32 + arow_l) * SROWB + ac4 * 8;
                *(uint2*)(dst + OFF_BH) = make_uint2(h0, h1);
                *(uint2*)(dst + OFF_BL) = make_uint2(l0, l1);
            }
        } else {
#pragma unroll
            for (int j = 0; j < 8; j++) {
                uint32_t h, l;
                pack2(bstgT[2 * j], bstgT[2 * j + 1], h, l);
                char* dst = smem + bn_l * SROWB + bkh * 32 + j * 4;
                *(uint32_t*)(dst + OFF_BH) = h;
                *(uint32_t*)(dst + OFF_BL) = l;
            }
        }
        __syncthreads();

        if (c + 1 < nchunks) {
            const int k0 = (c + 1) * 32;
#pragma unroll
            for (int p = 0; p < 4; p++)
                astg[p] = *(const float4*)(A + (size_t)(bm + p * 32 + arow_l) * lda + k0 + ac4 * 4);
            if (BNT) {
#pragma unroll
                for (int p = 0; p < 4; p++)
                    bstg[p] = *(const float4*)(B + (size_t)(bn + p * 32 + arow_l) * ldb + k0 + ac4 * 4);
            } else {
#pragma unroll
                for (int i = 0; i < 16; i++)
                    bstgT[i] = B[(size_t)(k0 + bkh * 16 + i) * ldb + bn + bn_l];
            }
        }

#pragma unroll
        for (int ks = 0; ks < 2; ks++) {
            uint32_t ah[4][4], al[4][4], bh[4][2], bl[4][2];
#pragma unroll
            for (int mt = 0; mt < 4; mt++) {
                uint32_t ad = a_off + (uint32_t)(mt * 16 * SROWB + ks * 32);
                ldsm_x4(ah[mt], ad + OFF_AH);
                ldsm_x4(al[mt], ad + OFF_AL);
            }
#pragma unroll
            for (int nt = 0; nt < 4; nt++) {
                uint32_t bd = b_off + (uint32_t)(nt * 8 * SROWB + ks * 32);
                ldsm_x2(bh[nt], bd + OFF_BH);
                ldsm_x2(bl[nt], bd + OFF_BL);
            }
#pragma unroll
            for (int mt = 0; mt < 4; mt++)
#pragma unroll
                for (int nt = 0; nt < 4; nt++) {
                    mma_bf16(acc[mt][nt], ah[mt], bh[nt]);
                    mma_bf16(acc[mt][nt], ah[mt], bl[nt]);
                    mma_bf16(acc[mt][nt], al[mt], bh[nt]);
                }
        }
        __syncthreads();
    }

#pragma unroll
    for (int mt = 0; mt < 4; mt++) {
#pragma unroll
        for (int nt = 0; nt < 4; nt++) {
            const int m0 = bm + wm * 64 + mt * 16 + (lane >> 2);
            const int n0 = bn + wn * 32 + nt * 8 + 2 * (lane & 3);
            float2 v0 = make_float2(acc[mt][nt][0], acc[mt][nt][1]);
            float2 v1 = make_float2(acc[mt][nt][2], acc[mt][nt][3]);
            if (BIAS) {
                float2 bb = *(const float2*)(bias + n0);
                v0.x += bb.x; v0.y += bb.y;
                v1.x += bb.x; v1.y += bb.y;
            }
            if (RES) {
                float2 r0 = *(const float2*)(res + (size_t)m0 * ldr + n0);
                float2 r1 = *(const float2*)(res + (size_t)(m0 + 8) * ldr + n0);
                v0.x += r0.x; v0.y += r0.y;
                v1.x += r1.x; v1.y += r1.y;
            }
            *(float2*)(C + (size_t)m0 * ldc + n0) = v0;
            *(float2*)(C + (size_t)(m0 + 8) * ldc + n0) = v1;
        }
    }
}

// ======================= HMMA flash attention (v2) ===========================
// grid (SEQ/64, NHEAD, BATCH), 128 threads (4 warps x 16 q-rows).
// K AND V both stored row-major (keys x dims) hi/lo — vectorized staging only.
// K B-fragments: ldsm_x4 (2 k-steps per load). V B-fragments: ldsm_x4.trans
// (2 n-tiles per load) — no scalar transpose stores.
#define TROWB 144                       // 64 bf16 = 128B + 16B pad
#define FKH 0
#define FKL (FKH + 64 * TROWB)
#define FVH (FKL + 64 * TROWB)
#define FVL (FVH + 64 * TROWB)
#define FLASH_SMEM (FVL + 64 * TROWB)   // 36864 B

__global__ __launch_bounds__(128)
void flash_mma(const float* __restrict__ Q, const float* __restrict__ Kp,
               const float* __restrict__ V, float* __restrict__ O)
{
    __shared__ char smem[FLASH_SMEM];
    const uint32_t sbase = smem_u32(smem);

    const int tid  = threadIdx.x;
    const int lane = tid & 31;
    const int w    = tid >> 5;          // warp 0..3 -> q rows 16w..16w+15
    const int h = blockIdx.y;
    const int b = blockIdx.z;
    const int bq = blockIdx.x * 64;

    const float* qbase = Q  + ((size_t)(b * SEQ + bq)) * E_DIM + h * HDIM;
    const float* kbase = Kp + ((size_t)b * SEQ) * E_DIM + h * HDIM;
    const float* vbase = V  + ((size_t)b * SEQ) * (3 * E_DIM) + h * HDIM;

    // ---- stage Q (scaled 1/8) into K region, extract A fragments ------------
#pragma unroll
    for (int it = 0; it < 8; it++) {
        int idx = tid + it * 128;
        int r  = idx >> 4;
        int c4 = idx & 15;
        float4 qv = *(const float4*)(qbase + (size_t)r * E_DIM + c4 * 4);
        uint32_t h0, l0, h1, l1;
        pack2(qv.x * 0.125f, qv.y * 0.125f, h0, l0);
        pack2(qv.z * 0.125f, qv.w * 0.125f, h1, l1);
        char* dst = smem + r * TROWB + c4 * 8;
        *(uint2*)(dst + FKH) = make_uint2(h0, h1);
        *(uint2*)(dst + FKL) = make_uint2(l0, l1);
    }
    __syncthreads();

    uint32_t qh[4][4], ql[4][4];
    {
        const uint32_t a_off = sbase + (uint32_t)((w * 16 + (lane & 15)) * TROWB + (lane >> 4) * 16);
#pragma unroll
        for (int ks = 0; ks < 4; ks++) {
            ldsm_x4(qh[ks], a_off + FKH + ks * 32);
            ldsm_x4(ql[ks], a_off + FKL + ks * 32);
        }
    }

    float o[8][4];
#pragma unroll
    for (int nt = 0; nt < 8; nt++)
#pragma unroll
        for (int t = 0; t < 4; t++) o[nt][t] = 0.f;
    float mrow[2] = {-1e30f, -1e30f};
    float lrow[2] = {0.f, 0.f};

    // K x4 base: m0/m1 = two 16B k-halves of ks-even, m2/m3 = ks-odd (+32B)
    const uint32_t kb4 = sbase + (uint32_t)((lane & 7) * TROWB + ((lane >> 3) & 1) * 16 + (lane >> 4) * 32);
    // V x4.trans base: m0 rows k..k+7, m1 rows +8; m2/m3 = dims +8 (+16B)
    const uint32_t vb4 = sbase + (uint32_t)(((lane & 7) + ((lane >> 3) & 1) * 8) * TROWB + (lane >> 4) * 16);

    for (int j0 = 0; j0 < SEQ; j0 += 64) {
        __syncthreads();
        // ---- stage K and V tiles (both row-major keys x dims, hi/lo) --------
#pragma unroll
        for (int it = 0; it < 8; it++) {
            int idx = tid + it * 128;
            int r  = idx >> 4;
            int c4 = idx & 15;
            float4 kv = *(const float4*)(kbase + (size_t)(j0 + r) * E_DIM + c4 * 4);
            uint32_t h0, l0, h1, l1;
            pack2(kv.x, kv.y, h0, l0);
            pack2(kv.z, kv.w, h1, l1);
            char* kd = smem + r * TROWB + c4 * 8;
            *(uint2*)(kd + FKH) = make_uint2(h0, h1);
            *(uint2*)(kd + FKL) = make_uint2(l0, l1);

            float4 vv = *(const float4*)(vbase + (size_t)(j0 + r) * (3 * E_DIM) + c4 * 4);
            pack2(vv.x, vv.y, h0, l0);
            pack2(vv.z, vv.w, h1, l1);
            char* vd = smem + r * TROWB + c4 * 8;
            *(uint2*)(vd + FVH) = make_uint2(h0, h1);
            *(uint2*)(vd + FVL) = make_uint2(l0, l1);
        }
        __syncthreads();

        // ---- S = Q K^T (fp32 accum, 3-term compensated) ---------------------
        float s[8][4];
#pragma unroll
        for (int nt = 0; nt < 8; nt++)
#pragma unroll
            for (int t = 0; t < 4; t++) s[nt][t] = 0.f;
#pragma unroll
        for (int ksp = 0; ksp < 2; ksp++) {
#pragma unroll
            for (int nt = 0; nt < 8; nt++) {
                uint32_t bd = kb4 + (uint32_t)(nt * 8 * TROWB + ksp * 64);
                uint32_t bh[4], bl[4];
                ldsm_x4(bh, bd + FKH);
                ldsm_x4(bl, bd + FKL);
                mma_bf16(s[nt], qh[2 * ksp],     bh);
                mma_bf16(s[nt], qh[2 * ksp],     bl);
                mma_bf16(s[nt], ql[2 * ksp],     bh);
                mma_bf16(s[nt], qh[2 * ksp + 1], bh + 2);
                mma_bf16(s[nt], qh[2 * ksp + 1], bl + 2);
                mma_bf16(s[nt], ql[2 * ksp + 1], bh + 2);
            }
        }

        // ---- online softmax --------------------------------------------------
#pragma unroll
        for (int r = 0; r < 2; r++) {
            const int off = 2 * r;
            float mx = s[0][off];
#pragma unroll
            for (int nt = 0; nt < 8; nt++) {
                mx = fmaxf(mx, s[nt][off]);
                mx = fmaxf(mx, s[nt][off + 1]);
            }
            mx = fmaxf(mx, __shfl_xor_sync(0xffffffffu, mx, 1));
            mx = fmaxf(mx, __shfl_xor_sync(0xffffffffu, mx, 2));
            float mnew = fmaxf(mrow[r], mx);
            float sc = __expf(mrow[r] - mnew);
            mrow[r] = mnew;
            float sum = 0.f;
#pragma unroll
            for (int nt = 0; nt < 8; nt++) {
                s[nt][off]     = __expf(s[nt][off]     - mnew);
                s[nt][off + 1] = __expf(s[nt][off + 1] - mnew);
                sum += s[nt][off] + s[nt][off + 1];
            }
            sum += __shfl_xor_sync(0xffffffffu, sum, 1);
            sum += __shfl_xor_sync(0xffffffffu, sum, 2);
            lrow[r] = lrow[r] * sc + sum;
#pragma unroll
            for (int nt = 0; nt < 8; nt++) {
                o[nt][off]     *= sc;
                o[nt][off + 1] *= sc;
            }
        }

        // ---- O += P V (V via ldsm.x4.trans, split hi/lo) ---------------------
#pragma unroll
        for (int ks = 0; ks < 4; ks++) {
            uint32_t pa[4], pl[4];
            pack2(s[2 * ks][0],     s[2 * ks][1],     pa[0], pl[0]);
            pack2(s[2 * ks][2],     s[2 * ks][3],     pa[1], pl[1]);
            pack2(s[2 * ks + 1][0], s[2 * ks + 1][1], pa[2], pl[2]);
            pack2(s[2 * ks + 1][2], s[2 * ks + 1][3], pa[3], pl[3]);
#pragma unroll
            for (int nt2 = 0; nt2 < 4; nt2++) {
                uint32_t vd = vb4 + (uint32_t)(ks * 16 * TROWB + nt2 * 32);
                uint32_t bh[4], bl[4];
                ldsm_x4t(bh, vd + FVH);
                ldsm_x4t(bl, vd + FVL);
                mma_bf16(o[2 * nt2], pa, bh);
                mma_bf16(o[2 * nt2], pa, bl);
                mma_bf16(o[2 * nt2], pl, bh);
                mma_bf16(o[2 * nt2 + 1], pa, bh + 2);
                mma_bf16(o[2 * nt2 + 1], pa, bl + 2);
                mma_bf16(o[2 * nt2 + 1], pl, bh + 2);
            }
        }
    }

    // ---- epilogue ------------------------------------------------------------
    const float inv0 = 1.f / lrow[0];
    const float inv1 = 1.f / lrow[1];
    const int m0 = b * SEQ + bq + w * 16 + (lane >> 2);
#pragma unroll
    for (int nt = 0; nt < 8; nt++) {
        const int n = h * HDIM + nt * 8 + 2 * (lane & 3);
        *(float2*)(O + (size_t)m0 * E_DIM + n) =
            make_float2(o[nt][0] * inv0, o[nt][1] * inv0);
        *(float2*)(O + (size_t)(m0 + 8) * E_DIM + n) =
            make_float2(o[nt][2] * inv1, o[nt][3] * inv1);
    }
}

// ---------------- launcher ---------------------------------------------------
extern "C" void kernel_launch(void* const* d_in, const int* in_sizes, int n_in,
                              void* d_out, int out_size)
{
    (void)in_sizes; (void)n_in; (void)out_size;
    const float* x    = (const float*)d_in[0];
    const float* rot  = (const float*)d_in[1];
    const float* ent  = (const float*)d_in[2];
    const float* qkvw = (const float*)d_in[3];
    const float* qkvb = (const float*)d_in[4];
    const float* outw = (const float*)d_in[5];
    const float* outb = (const float*)d_in[6];
    float* out = (float*)d_out;

    float *qkv, *q, *k, *o;
    cudaGetSymbolAddress((void**)&qkv, g_qkv);
    cudaGetSymbolAddress((void**)&q,   g_q);
    cudaGetSymbolAddress((void**)&k,   g_k);
    cudaGetSymbolAddress((void**)&o,   g_o);

    // 1) qkv = x @ qkv_w^T + qkv_b   (4096 x 3072 x 1024, NT)
    hgemm<1, 1, 0><<<dim3(3 * E_DIM / 128, MROWS / 128), 256>>>(
        x, E_DIM, qkvw, E_DIM, qkvb, nullptr, 0, qkv, 3 * E_DIM, E_DIM);

    // 2) q' = qkv[:, 0:1024] @ rotation   (NN)
    hgemm<0, 0, 0><<<dim3(E_DIM / 128, MROWS / 128), 256>>>(
        qkv, 3 * E_DIM, rot, E_DIM, nullptr, nullptr, 0, q, E_DIM, E_DIM);

    // 3) k' = qkv[:, 1024:2048] @ entangle (NN)
    hgemm<0, 0, 0><<<dim3(E_DIM / 128, MROWS / 128), 256>>>(
        qkv + E_DIM, 3 * E_DIM, ent, E_DIM, nullptr, nullptr, 0, k, E_DIM, E_DIM);

    // 4) attention (HMMA): O = softmax(q' k'^T / 8) @ v
    flash_mma<<<dim3(SEQ / 64, NHEAD, BATCH), 128>>>(
        q, k, qkv + 2 * E_DIM, o);

    // 5) out = O @ out_w^T + out_b + x    (NT + bias + residual)
    hgemm<1, 1, 1><<<dim3(E_DIM / 128, MROWS / 128), 256>>>(
        o, E_DIM, outw, E_DIM, outb, x, E_DIM, out, E_DIM, E_DIM);
}

// round 7
// speedup vs baseline: 3.5228x; 1.1799x over previous
#include <cuda_runtime.h>
#include <cuda_bf16.h>
#include <cstdint>
#include <math.h>

#define E_DIM 1024
#define NHEAD 16
#define HDIM  64
#define BATCH 2
#define SEQ   2048
#define MROWS (BATCH * SEQ)   // 4096

// ---------------- bf16 hi/lo plane scratch (lo plane at +N elements) --------
__device__ uint16_t g_xb  [2u * MROWS * E_DIM];      // x
__device__ uint16_t g_wqkv[2u * 3 * E_DIM * E_DIM];  // qkv_w (N,K)
__device__ uint16_t g_rotT[2u * E_DIM * E_DIM];      // rotation^T (N,K)
__device__ uint16_t g_entT[2u * E_DIM * E_DIM];      // entangle^T (N,K)
__device__ uint16_t g_wout[2u * E_DIM * E_DIM];      // out_w (N,K)
__device__ uint16_t g_aq  [2u * MROWS * E_DIM];      // qkv[:, 0:1024]
__device__ uint16_t g_ak  [2u * MROWS * E_DIM];      // qkv[:, 1024:2048]
__device__ uint16_t g_v   [2u * MROWS * E_DIM];      // qkv[:, 2048:3072]
__device__ uint16_t g_qp  [2u * MROWS * E_DIM];      // q' (pre-scaled 1/8)
__device__ uint16_t g_kp  [2u * MROWS * E_DIM];      // k'
__device__ uint16_t g_ob  [2u * MROWS * E_DIM];      // attention out

// ======================= mma.sync helpers ===================================
__device__ __forceinline__ uint32_t smem_u32(const void* p) {
    uint32_t a;
    asm("{ .reg .u64 t; cvta.to.shared.u64 t, %1; cvt.u32.u64 %0, t; }" : "=r"(a) : "l"(p));
    return a;
}
__device__ __forceinline__ void ldsm_x4(uint32_t* r, uint32_t addr) {
    asm volatile("ldmatrix.sync.aligned.m8n8.x4.shared.b16 {%0,%1,%2,%3}, [%4];"
                 : "=r"(r[0]), "=r"(r[1]), "=r"(r[2]), "=r"(r[3]) : "r"(addr));
}
__device__ __forceinline__ void ldsm_x4t(uint32_t* r, uint32_t addr) {
    asm volatile("ldmatrix.sync.aligned.m8n8.x4.trans.shared.b16 {%0,%1,%2,%3}, [%4];"
                 : "=r"(r[0]), "=r"(r[1]), "=r"(r[2]), "=r"(r[3]) : "r"(addr));
}
__device__ __forceinline__ void mma_bf16(float* c, const uint32_t* a, const uint32_t* b) {
    asm volatile(
        "mma.sync.aligned.m16n8k16.row.col.f32.bf16.bf16.f32 "
        "{%0,%1,%2,%3}, {%4,%5,%6,%7}, {%8,%9}, {%0,%1,%2,%3};"
        : "+f"(c[0]), "+f"(c[1]), "+f"(c[2]), "+f"(c[3])
        : "r"(a[0]), "r"(a[1]), "r"(a[2]), "r"(a[3]), "r"(b[0]), "r"(b[1]));
}
__device__ __forceinline__ void split1(float v, uint16_t& h, uint16_t& l) {
    __nv_bfloat16 hb = __float2bfloat16_rn(v);
    float r = v - __bfloat162float(hb);
    __nv_bfloat16 lb = __float2bfloat16_rn(r);
    h = *reinterpret_cast<uint16_t*>(&hb);
    l = *reinterpret_cast<uint16_t*>(&lb);
}
__device__ __forceinline__ void pack2(float a, float b, uint32_t& hi, uint32_t& lo) {
    uint16_t ha, la, hb, lb;
    split1(a, ha, la);
    split1(b, hb, lb);
    hi = (uint32_t)ha | ((uint32_t)hb << 16);
    lo = (uint32_t)la | ((uint32_t)lb << 16);
}

// ======================= convert kernels ====================================
// fp32 -> hi/lo bf16 planes (lo at +n elements)
__global__ void conv_split(const float* __restrict__ src, uint16_t* __restrict__ dst, int n)
{
    int n4 = n >> 2;
    for (int i = blockIdx.x * blockDim.x + threadIdx.x; i < n4; i += gridDim.x * blockDim.x) {
        float4 v = ((const float4*)src)[i];
        uint32_t h0, l0, h1, l1;
        pack2(v.x, v.y, h0, l0);
        pack2(v.z, v.w, h1, l1);
        ((uint2*)dst)[i] = make_uint2(h0, h1);
        ((uint2*)(dst + n))[i] = make_uint2(l0, l1);
    }
}
// fp32 (K=1024, N=1024) row-major -> TRANSPOSED hi/lo planes (N,K)
__global__ void convT_split(const float* __restrict__ src, uint16_t* __restrict__ dst)
{
    __shared__ float t[32][33];
    const int tx = threadIdx.x, ty = threadIdx.y;
    const int n0 = blockIdx.x * 32, k0 = blockIdx.y * 32;
#pragma unroll
    for (int j = 0; j < 4; j++)
        t[ty * 4 + j][tx] = src[(size_t)(k0 + ty * 4 + j) * E_DIM + n0 + tx];
    __syncthreads();
#pragma unroll
    for (int j = 0; j < 4; j++) {
        int n = n0 + ty * 4 + j, k = k0 + tx;
        uint16_t h, l;
        split1(t[tx][ty * 4 + j], h, l);
        dst[(size_t)n * E_DIM + k] = h;
        dst[(size_t)E_DIM * E_DIM + (size_t)n * E_DIM + k] = l;
    }
}

// ======================= bf16-plane HMMA GEMM ===============================
// C = A @ B^T; A (M,K) planes, B (N,K) planes. 128x128 tile, BK=32, 256 thr.
// MODE 0: C fp32 = acc + bias + res        (final projection)
// MODE 1: P0 planes = (acc * scale)        (rotation / entangle)
// MODE 2: planes P[n>>10] = acc + bias     (qkv -> q/k/v planes)
#define SROWB 80
#define OFF_AH 0
#define OFF_AL (OFF_AH + 128 * SROWB)
#define OFF_BH (OFF_AL + 128 * SROWB)
#define OFF_BL (OFF_BH + 128 * SROWB)
#define GEMM_SMEM (OFF_BL + 128 * SROWB)

template<int MODE>
__global__ __launch_bounds__(256)
void hgemm_bf16(const uint16_t* __restrict__ Ah, const uint16_t* __restrict__ Al, int lda,
                const uint16_t* __restrict__ Bh, const uint16_t* __restrict__ Bl, int ldb,
                const float* __restrict__ bias,
                const float* __restrict__ res, int ldr,
                float* __restrict__ C, int ldc,
                uint16_t* __restrict__ P0h, uint16_t* __restrict__ P0l,
                uint16_t* __restrict__ P1h, uint16_t* __restrict__ P1l,
                uint16_t* __restrict__ P2h, uint16_t* __restrict__ P2l, int ldp,
                float scale, int K)
{
    __shared__ char smem[GEMM_SMEM];
    const uint32_t sbase = smem_u32(smem);

    const int tid  = threadIdx.x;
    const int lane = tid & 31;
    const int wid  = tid >> 5;
    const int wm   = wid >> 2;
    const int wn   = wid & 3;
    const int bm   = blockIdx.y * 128;
    const int bn   = blockIdx.x * 128;

    const int lrow = tid >> 2;          // 0..63
    const int lc8  = tid & 3;           // uint4 (8 bf16) column group

    const uint16_t* pah = Ah + (size_t)(bm + lrow) * lda + lc8 * 8;
    const uint16_t* pal = Al + (size_t)(bm + lrow) * lda + lc8 * 8;
    const uint16_t* pbh = Bh + (size_t)(bn + lrow) * ldb + lc8 * 8;
    const uint16_t* pbl = Bl + (size_t)(bn + lrow) * ldb + lc8 * 8;
    const size_t half = (size_t)64 * lda;   // lda == ldb for all our calls
    const size_t halfb = (size_t)64 * ldb;

    float acc[4][4][4];
#pragma unroll
    for (int i = 0; i < 4; i++)
#pragma unroll
        for (int j = 0; j < 4; j++)
#pragma unroll
            for (int t = 0; t < 4; t++) acc[i][j][t] = 0.f;

    const uint32_t a4 = sbase + (uint32_t)((wm * 64 + (lane & 15)) * SROWB + (lane >> 4) * 16);
    const uint32_t b4 = sbase + (uint32_t)((wn * 32 + (lane & 7)) * SROWB + ((lane >> 3) & 1) * 16 + (lane >> 4) * 32);

    const int nchunks = K / 32;

    uint4 sa0, sa1, sa2, sa3, sb0, sb1, sb2, sb3;
    sa0 = *(const uint4*)(pah);         sa1 = *(const uint4*)(pah + half);
    sa2 = *(const uint4*)(pal);         sa3 = *(const uint4*)(pal + half);
    sb0 = *(const uint4*)(pbh);         sb1 = *(const uint4*)(pbh + halfb);
    sb2 = *(const uint4*)(pbl);         sb3 = *(const uint4*)(pbl + halfb);

    char* sd = smem + lrow * SROWB + lc8 * 16;

    for (int c = 0; c < nchunks; c++) {
        *(uint4*)(sd + OFF_AH) = sa0;   *(uint4*)(sd + OFF_AH + 64 * SROWB) = sa1;
        *(uint4*)(sd + OFF_AL) = sa2;   *(uint4*)(sd + OFF_AL + 64 * SROWB) = sa3;
        *(uint4*)(sd + OFF_BH) = sb0;   *(uint4*)(sd + OFF_BH + 64 * SROWB) = sb1;
        *(uint4*)(sd + OFF_BL) = sb2;   *(uint4*)(sd + OFF_BL + 64 * SROWB) = sb3;
        __syncthreads();

        if (c + 1 < nchunks) {
            const int k0 = (c + 1) * 32;
            sa0 = *(const uint4*)(pah + k0);         sa1 = *(const uint4*)(pah + half + k0);
            sa2 = *(const uint4*)(pal + k0);         sa3 = *(const uint4*)(pal + half + k0);
            sb0 = *(const uint4*)(pbh + k0);         sb1 = *(const uint4*)(pbh + halfb + k0);
            sb2 = *(const uint4*)(pbl + k0);         sb3 = *(const uint4*)(pbl + halfb + k0);
        }

        uint32_t bh4[4][4], bl4[4][4];
#pragma unroll
        for (int nt = 0; nt < 4; nt++) {
            ldsm_x4(bh4[nt], b4 + nt * 8 * SROWB + OFF_BH);
            ldsm_x4(bl4[nt], b4 + nt * 8 * SROWB + OFF_BL);
        }
#pragma unroll
        for (int ks = 0; ks < 2; ks++) {
            uint32_t ah[4][4], al[4][4];
#pragma unroll
            for (int mt = 0; mt < 4; mt++) {
                ldsm_x4(ah[mt], a4 + mt * 16 * SROWB + ks * 32 + OFF_AH);
                ldsm_x4(al[mt], a4 + mt * 16 * SROWB + ks * 32 + OFF_AL);
            }
#pragma unroll
            for (int mt = 0; mt < 4; mt++)
#pragma unroll
                for (int nt = 0; nt < 4; nt++) {
                    mma_bf16(acc[mt][nt], ah[mt], &bh4[nt][2 * ks]);
                    mma_bf16(acc[mt][nt], ah[mt], &bl4[nt][2 * ks]);
                    mma_bf16(acc[mt][nt], al[mt], &bh4[nt][2 * ks]);
                }
        }
        __syncthreads();
    }

    // ---- epilogue -----------------------------------------------------------
    uint16_t *ph = P0h, *pl = P0l;
    if (MODE == 2) {
        const int part = bn >> 10;
        ph = (part == 0) ? P0h : (part == 1) ? P1h : P2h;
        pl = (part == 0) ? P0l : (part == 1) ? P1l : P2l;
    }
#pragma unroll
    for (int mt = 0; mt < 4; mt++) {
#pragma unroll
        for (int nt = 0; nt < 4; nt++) {
            const int m0 = bm + wm * 64 + mt * 16 + (lane >> 2);
            const int n0 = bn + wn * 32 + nt * 8 + 2 * (lane & 3);
            float2 v0 = make_float2(acc[mt][nt][0], acc[mt][nt][1]);
            float2 v1 = make_float2(acc[mt][nt][2], acc[mt][nt][3]);
            if (MODE == 0) {
                float2 bb = *(const float2*)(bias + n0);
                float2 r0 = *(const float2*)(res + (size_t)m0 * ldr + n0);
                float2 r1 = *(const float2*)(res + (size_t)(m0 + 8) * ldr + n0);
                v0.x += bb.x + r0.x; v0.y += bb.y + r0.y;
                v1.x += bb.x + r1.x; v1.y += bb.y + r1.y;
                *(float2*)(C + (size_t)m0 * ldc + n0) = v0;
                *(float2*)(C + (size_t)(m0 + 8) * ldc + n0) = v1;
            } else {
                if (MODE == 2) {
                    float2 bb = *(const float2*)(bias + n0);
                    v0.x += bb.x; v0.y += bb.y;
                    v1.x += bb.x; v1.y += bb.y;
                } else {
                    v0.x *= scale; v0.y *= scale;
                    v1.x *= scale; v1.y *= scale;
                }
                const int nc = (MODE == 2) ? (n0 & 1023) : n0;
                uint32_t h0, l0, h1, l1;
                pack2(v0.x, v0.y, h0, l0);
                pack2(v1.x, v1.y, h1, l1);
                *(uint32_t*)(ph + (size_t)m0 * ldp + nc) = h0;
                *(uint32_t*)(pl + (size_t)m0 * ldp + nc) = l0;
                *(uint32_t*)(ph + (size_t)(m0 + 8) * ldp + nc) = h1;
                *(uint32_t*)(pl + (size_t)(m0 + 8) * ldp + nc) = l1;
            }
        }
    }
}

// ======================= HMMA flash attention (bf16 planes) ==================
// grid (SEQ/64, NHEAD, BATCH), 128 threads (4 warps x 16 q-rows).
// Q pre-scaled by 1/8; Q/K/V loaded from hi/lo planes; O written as planes.
#define TROWB 144
#define FKH 0
#define FKL (FKH + 64 * TROWB)
#define FVH (FKL + 64 * TROWB)
#define FVL (FVH + 64 * TROWB)
#define FLASH_SMEM (FVL + 64 * TROWB)

__global__ __launch_bounds__(128)
void flash_bf16(const uint16_t* __restrict__ Qh, const uint16_t* __restrict__ Ql,
                const uint16_t* __restrict__ Kh, const uint16_t* __restrict__ Kl,
                const uint16_t* __restrict__ Vh, const uint16_t* __restrict__ Vl,
                uint16_t* __restrict__ Oh, uint16_t* __restrict__ Ol)
{
    __shared__ char smem[FLASH_SMEM];
    const uint32_t sbase = smem_u32(smem);

    const int tid  = threadIdx.x;
    const int lane = tid & 31;
    const int w    = tid >> 5;
    const int h = blockIdx.y;
    const int b = blockIdx.z;
    const int bq = blockIdx.x * 64;

    const size_t qrow0 = (size_t)(b * SEQ + bq);
    const size_t krow0 = (size_t)b * SEQ;
    const int hc = h * HDIM;

    // ---- stage Q planes into K region, extract A fragments ------------------
    {
        const int r  = tid >> 1;            // 0..63
        const int c8h = (tid & 1) * 4;      // uint4 group 0..3 / 4..7
#pragma unroll
        for (int g = 0; g < 4; g++) {
            const uint16_t* src = Qh + (qrow0 + r) * E_DIM + hc + (c8h + g) * 8;
            *(uint4*)(smem + r * TROWB + (c8h + g) * 16 + FKH) = *(const uint4*)src;
            src = Ql + (qrow0 + r) * E_DIM + hc + (c8h + g) * 8;
            *(uint4*)(smem + r * TROWB + (c8h + g) * 16 + FKL) = *(const uint4*)src;
        }
    }
    __syncthreads();

    uint32_t qh[4][4], ql[4][4];
    {
        const uint32_t a_off = sbase + (uint32_t)((w * 16 + (lane & 15)) * TROWB + (lane >> 4) * 16);
#pragma unroll
        for (int ks = 0; ks < 4; ks++) {
            ldsm_x4(qh[ks], a_off + FKH + ks * 32);
            ldsm_x4(ql[ks], a_off + FKL + ks * 32);
        }
    }

    float o[8][4];
#pragma unroll
    for (int nt = 0; nt < 8; nt++)
#pragma unroll
        for (int t = 0; t < 4; t++) o[nt][t] = 0.f;
    float mrow[2] = {-1e30f, -1e30f};
    float lrow[2] = {0.f, 0.f};

    const uint32_t kb4 = sbase + (uint32_t)((lane & 7) * TROWB + ((lane >> 3) & 1) * 16 + (lane >> 4) * 32);
    const uint32_t vb4 = sbase + (uint32_t)(((lane & 7) + ((lane >> 3) & 1) * 8) * TROWB + (lane >> 4) * 16);

    const int r  = tid >> 1;
    const int c8h = (tid & 1) * 4;

    for (int j0 = 0; j0 < SEQ; j0 += 64) {
        __syncthreads();
        // ---- stage K and V hi/lo tiles (vectorized, no conversion) ----------
        {
            const size_t rg = (krow0 + j0 + r) * E_DIM + hc;
#pragma unroll
            for (int g = 0; g < 4; g++) {
                const int co = (c8h + g) * 8, bo = (c8h + g) * 16;
                *(uint4*)(smem + r * TROWB + bo + FKH) = *(const uint4*)(Kh + rg + co);
                *(uint4*)(smem + r * TROWB + bo + FKL) = *(const uint4*)(Kl + rg + co);
                *(uint4*)(smem + r * TROWB + bo + FVH) = *(const uint4*)(Vh + rg + co);
                *(uint4*)(smem + r * TROWB + bo + FVL) = *(const uint4*)(Vl + rg + co);
            }
        }
        __syncthreads();

        // ---- S = Q K^T ------------------------------------------------------
        float s[8][4];
#pragma unroll
        for (int nt = 0; nt < 8; nt++)
#pragma unroll
            for (int t = 0; t < 4; t++) s[nt][t] = 0.f;
#pragma unroll
        for (int ksp = 0; ksp < 2; ksp++) {
#pragma unroll
            for (int nt = 0; nt < 8; nt++) {
                uint32_t bd = kb4 + (uint32_t)(nt * 8 * TROWB + ksp * 64);
                uint32_t bh[4], bl[4];
                ldsm_x4(bh, bd + FKH);
                ldsm_x4(bl, bd + FKL);
                mma_bf16(s[nt], qh[2 * ksp],     bh);
                mma_bf16(s[nt], qh[2 * ksp],     bl);
                mma_bf16(s[nt], ql[2 * ksp],     bh);
                mma_bf16(s[nt], qh[2 * ksp + 1], bh + 2);
                mma_bf16(s[nt], qh[2 * ksp + 1], bl + 2);
                mma_bf16(s[nt], ql[2 * ksp + 1], bh + 2);
            }
        }

        // ---- online softmax -------------------------------------------------
#pragma unroll
        for (int rr = 0; rr < 2; rr++) {
            const int off = 2 * rr;
            float mx = s[0][off];
#pragma unroll
            for (int nt = 0; nt < 8; nt++) {
                mx = fmaxf(mx, s[nt][off]);
                mx = fmaxf(mx, s[nt][off + 1]);
            }
            mx = fmaxf(mx, __shfl_xor_sync(0xffffffffu, mx, 1));
            mx = fmaxf(mx, __shfl_xor_sync(0xffffffffu, mx, 2));
            float mnew = fmaxf(mrow[rr], mx);
            float sc = __expf(mrow[rr] - mnew);
            mrow[rr] = mnew;
            float sum = 0.f;
#pragma unroll
            for (int nt = 0; nt < 8; nt++) {
                s[nt][off]     = __expf(s[nt][off]     - mnew);
                s[nt][off + 1] = __expf(s[nt][off + 1] - mnew);
                sum += s[nt][off] + s[nt][off + 1];
            }
            sum += __shfl_xor_sync(0xffffffffu, sum, 1);
            sum += __shfl_xor_sync(0xffffffffu, sum, 2);
            lrow[rr] = lrow[rr] * sc + sum;
#pragma unroll
            for (int nt = 0; nt < 8; nt++) {
                o[nt][off]     *= sc;
                o[nt][off + 1] *= sc;
            }
        }

        // ---- O += P V -------------------------------------------------------
#pragma unroll
        for (int ks = 0; ks < 4; ks++) {
            uint32_t pa[4], pl2[4];
            pack2(s[2 * ks][0],     s[2 * ks][1],     pa[0], pl2[0]);
            pack2(s[2 * ks][2],     s[2 * ks][3],     pa[1], pl2[1]);
            pack2(s[2 * ks + 1][0], s[2 * ks + 1][1], pa[2], pl2[2]);
            pack2(s[2 * ks + 1][2], s[2 * ks + 1][3], pa[3], pl2[3]);
#pragma unroll
            for (int nt2 = 0; nt2 < 4; nt2++) {
                uint32_t vd = vb4 + (uint32_t)(ks * 16 * TROWB + nt2 * 32);
                uint32_t bh[4], bl[4];
                ldsm_x4t(bh, vd + FVH);
                ldsm_x4t(bl, vd + FVL);
                mma_bf16(o[2 * nt2], pa, bh);
                mma_bf16(o[2 * nt2], pa, bl);
                mma_bf16(o[2 * nt2], pl2, bh);
                mma_bf16(o[2 * nt2 + 1], pa, bh + 2);
                mma_bf16(o[2 * nt2 + 1], pa, bl + 2);
                mma_bf16(o[2 * nt2 + 1], pl2, bh + 2);
            }
        }
    }

    // ---- epilogue: write O planes -------------------------------------------
    const float inv0 = 1.f / lrow[0];
    const float inv1 = 1.f / lrow[1];
    const size_t m0 = qrow0 + w * 16 + (lane >> 2);
#pragma unroll
    for (int nt = 0; nt < 8; nt++) {
        const int n = hc + nt * 8 + 2 * (lane & 3);
        uint32_t h0, l0, h1, l1;
        pack2(o[nt][0] * inv0, o[nt][1] * inv0, h0, l0);
        pack2(o[nt][2] * inv1, o[nt][3] * inv1, h1, l1);
        *(uint32_t*)(Oh + m0 * E_DIM + n) = h0;
        *(uint32_t*)(Ol + m0 * E_DIM + n) = l0;
        *(uint32_t*)(Oh + (m0 + 8) * E_DIM + n) = h1;
        *(uint32_t*)(Ol + (m0 + 8) * E_DIM + n) = l1;
    }
}

// ---------------- launcher ---------------------------------------------------
extern "C" void kernel_launch(void* const* d_in, const int* in_sizes, int n_in,
                              void* d_out, int out_size)
{
    (void)in_sizes; (void)n_in; (void)out_size;
    const float* x    = (const float*)d_in[0];
    const float* rot  = (const float*)d_in[1];
    const float* ent  = (const float*)d_in[2];
    const float* qkvw = (const float*)d_in[3];
    const float* qkvb = (const float*)d_in[4];
    const float* outw = (const float*)d_in[5];
    const float* outb = (const float*)d_in[6];
    float* out = (float*)d_out;

    uint16_t *xb, *wqkv, *rotT, *entT, *wout, *aq, *ak, *v, *qp, *kp, *ob;
    cudaGetSymbolAddress((void**)&xb,   g_xb);
    cudaGetSymbolAddress((void**)&wqkv, g_wqkv);
    cudaGetSymbolAddress((void**)&rotT, g_rotT);
    cudaGetSymbolAddress((void**)&entT, g_entT);
    cudaGetSymbolAddress((void**)&wout, g_wout);
    cudaGetSymbolAddress((void**)&aq,   g_aq);
    cudaGetSymbolAddress((void**)&ak,   g_ak);
    cudaGetSymbolAddress((void**)&v,    g_v);
    cudaGetSymbolAddress((void**)&qp,   g_qp);
    cudaGetSymbolAddress((void**)&kp,   g_kp);
    cudaGetSymbolAddress((void**)&ob,   g_ob);

    const int NX  = MROWS * E_DIM;       // 4M
    const int NW3 = 3 * E_DIM * E_DIM;   // 3M
    const int NW  = E_DIM * E_DIM;       // 1M

    // 0) one-time splits (per launch; cheap, memory-bound)
    conv_split<<<512, 256>>>(x,    xb,   NX);
    conv_split<<<512, 256>>>(qkvw, wqkv, NW3);
    conv_split<<<256, 256>>>(outw, wout, NW);
    convT_split<<<dim3(32, 32), dim3(32, 8)>>>(rot, rotT);
    convT_split<<<dim3(32, 32), dim3(32, 8)>>>(ent, entT);

    // 1) qkv = x @ qkv_w^T + qkv_b  ->  q/k/v planes
    hgemm_bf16<2><<<dim3(3 * E_DIM / 128, MROWS / 128), 256>>>(
        xb, xb + NX, E_DIM, wqkv, wqkv + NW3, E_DIM,
        qkvb, nullptr, 0, nullptr, 0,
        aq, aq + NX, ak, ak + NX, v, v + NX, E_DIM, 1.f, E_DIM);

    // 2) q' = q @ rotation (pre-scaled 1/8) -> Q planes
    hgemm_bf16<1><<<dim3(E_DIM / 128, MROWS / 128), 256>>>(
        aq, aq + NX, E_DIM, rotT, rotT + NW, E_DIM,
        nullptr, nullptr, 0, nullptr, 0,
        qp, qp + NX, nullptr, nullptr, nullptr, nullptr, E_DIM, 0.125f, E_DIM);

    // 3) k' = k @ entangle -> K planes
    hgemm_bf16<1><<<dim3(E_DIM / 128, MROWS / 128), 256>>>(
        ak, ak + NX, E_DIM, entT, entT + NW, E_DIM,
        nullptr, nullptr, 0, nullptr, 0,
        kp, kp + NX, nullptr, nullptr, nullptr, nullptr, E_DIM, 1.f, E_DIM);

    // 4) attention -> O planes
    flash_bf16<<<dim3(SEQ / 64, NHEAD, BATCH), 128>>>(
        qp, qp + NX, kp, kp + NX, v, v + NX, ob, ob + NX);

    // 5) out = O @ out_w^T + out_b + x
    hgemm_bf16<0><<<dim3(E_DIM / 128, MROWS / 128), 256>>>(
        ob, ob + NX, E_DIM, wout, wout + NW, E_DIM,
        outb, x, E_DIM, out, E_DIM,
        nullptr, nullptr, nullptr, nullptr, nullptr, nullptr, 0, 1.f, E_DIM);
}

// round 8
// speedup vs baseline: 3.6295x; 1.0303x over previous
#include <cuda_runtime.h>
#include <cuda_bf16.h>
#include <cstdint>
#include <math.h>

#define E_DIM 1024
#define NHEAD 16
#define HDIM  64
#define BATCH 2
#define SEQ   2048
#define MROWS (BATCH * SEQ)   // 4096

// ---------------- bf16 hi/lo plane scratch (lo plane at +N elements) --------
__device__ uint16_t g_xb  [2u * MROWS * E_DIM];
__device__ uint16_t g_wqkv[2u * 3 * E_DIM * E_DIM];
__device__ uint16_t g_rotT[2u * E_DIM * E_DIM];
__device__ uint16_t g_entT[2u * E_DIM * E_DIM];
__device__ uint16_t g_wout[2u * E_DIM * E_DIM];
__device__ uint16_t g_aq  [2u * MROWS * E_DIM];
__device__ uint16_t g_ak  [2u * MROWS * E_DIM];
__device__ uint16_t g_v   [2u * MROWS * E_DIM];
__device__ uint16_t g_qp  [2u * MROWS * E_DIM];
__device__ uint16_t g_kp  [2u * MROWS * E_DIM];
__device__ uint16_t g_ob  [2u * MROWS * E_DIM];

// ======================= helpers ============================================
__device__ __forceinline__ uint32_t smem_u32(const void* p) {
    uint32_t a;
    asm("{ .reg .u64 t; cvta.to.shared.u64 t, %1; cvt.u32.u64 %0, t; }" : "=r"(a) : "l"(p));
    return a;
}
__device__ __forceinline__ void ldsm_x4(uint32_t* r, uint32_t addr) {
    asm volatile("ldmatrix.sync.aligned.m8n8.x4.shared.b16 {%0,%1,%2,%3}, [%4];"
                 : "=r"(r[0]), "=r"(r[1]), "=r"(r[2]), "=r"(r[3]) : "r"(addr));
}
__device__ __forceinline__ void ldsm_x4t(uint32_t* r, uint32_t addr) {
    asm volatile("ldmatrix.sync.aligned.m8n8.x4.trans.shared.b16 {%0,%1,%2,%3}, [%4];"
                 : "=r"(r[0]), "=r"(r[1]), "=r"(r[2]), "=r"(r[3]) : "r"(addr));
}
__device__ __forceinline__ void mma_bf16(float* c, const uint32_t* a, const uint32_t* b) {
    asm volatile(
        "mma.sync.aligned.m16n8k16.row.col.f32.bf16.bf16.f32 "
        "{%0,%1,%2,%3}, {%4,%5,%6,%7}, {%8,%9}, {%0,%1,%2,%3};"
        : "+f"(c[0]), "+f"(c[1]), "+f"(c[2]), "+f"(c[3])
        : "r"(a[0]), "r"(a[1]), "r"(a[2]), "r"(a[3]), "r"(b[0]), "r"(b[1]));
}
__device__ __forceinline__ void split1(float v, uint16_t& h, uint16_t& l) {
    __nv_bfloat16 hb = __float2bfloat16_rn(v);
    float r = v - __bfloat162float(hb);
    __nv_bfloat16 lb = __float2bfloat16_rn(r);
    h = *reinterpret_cast<uint16_t*>(&hb);
    l = *reinterpret_cast<uint16_t*>(&lb);
}
__device__ __forceinline__ void pack2(float a, float b, uint32_t& hi, uint32_t& lo) {
    uint16_t ha, la, hb, lb;
    split1(a, ha, la);
    split1(b, hb, lb);
    hi = (uint32_t)ha | ((uint32_t)hb << 16);
    lo = (uint32_t)la | ((uint32_t)lb << 16);
}
__device__ __forceinline__ void cp16(uint32_t dst, const void* src) {
    asm volatile("cp.async.cg.shared.global [%0], [%1], 16;" :: "r"(dst), "l"(src));
}
#define CP_COMMIT() asm volatile("cp.async.commit_group;" ::: "memory")
#define CP_WAIT1()  asm volatile("cp.async.wait_group 1;" ::: "memory")
#define CP_WAIT0()  asm volatile("cp.async.wait_group 0;" ::: "memory")

// ======================= convert kernels ====================================
__global__ void conv_split(const float* __restrict__ src, uint16_t* __restrict__ dst, int n)
{
    int n4 = n >> 2;
    for (int i = blockIdx.x * blockDim.x + threadIdx.x; i < n4; i += gridDim.x * blockDim.x) {
        float4 v = ((const float4*)src)[i];
        uint32_t h0, l0, h1, l1;
        pack2(v.x, v.y, h0, l0);
        pack2(v.z, v.w, h1, l1);
        ((uint2*)dst)[i] = make_uint2(h0, h1);
        ((uint2*)(dst + n))[i] = make_uint2(l0, l1);
    }
}
__global__ void convT_split(const float* __restrict__ src, uint16_t* __restrict__ dst)
{
    __shared__ float t[32][33];
    const int tx = threadIdx.x, ty = threadIdx.y;
    const int n0 = blockIdx.x * 32, k0 = blockIdx.y * 32;
#pragma unroll
    for (int j = 0; j < 4; j++)
        t[ty * 4 + j][tx] = src[(size_t)(k0 + ty * 4 + j) * E_DIM + n0 + tx];
    __syncthreads();
#pragma unroll
    for (int j = 0; j < 4; j++) {
        int n = n0 + ty * 4 + j, k = k0 + tx;
        uint16_t h, l;
        split1(t[tx][ty * 4 + j], h, l);
        dst[(size_t)n * E_DIM + k] = h;
        dst[(size_t)E_DIM * E_DIM + (size_t)n * E_DIM + k] = l;
    }
}

// ======================= bf16-plane HMMA GEMM (cp.async 2-stage) ============
#define SROWB 80
#define GPLANE (128 * SROWB)        // 10240
#define GSTAGE (4 * GPLANE)         // 40960
#define GEMM_SMEM (2 * GSTAGE)      // 81920
// plane offsets within a stage
#define PAH 0
#define PAL GPLANE
#define PBH (2 * GPLANE)
#define PBL (3 * GPLANE)

template<int MODE>
__global__ __launch_bounds__(256)
void hgemm_bf16(const uint16_t* __restrict__ Ah, const uint16_t* __restrict__ Al, int lda,
                const uint16_t* __restrict__ Bh, const uint16_t* __restrict__ Bl, int ldb,
                const float* __restrict__ bias,
                const float* __restrict__ res, int ldr,
                float* __restrict__ C, int ldc,
                uint16_t* __restrict__ P0h, uint16_t* __restrict__ P0l,
                uint16_t* __restrict__ P1h, uint16_t* __restrict__ P1l,
                uint16_t* __restrict__ P2h, uint16_t* __restrict__ P2l, int ldp,
                float scale, int K)
{
    extern __shared__ char smem[];
    const uint32_t sbase = smem_u32(smem);

    const int tid  = threadIdx.x;
    const int lane = tid & 31;
    const int wid  = tid >> 5;
    const int wm   = wid >> 2;
    const int wn   = wid & 3;
    const int bm   = blockIdx.y * 128;
    const int bn   = blockIdx.x * 128;

    float acc[4][4][4];
#pragma unroll
    for (int i = 0; i < 4; i++)
#pragma unroll
        for (int j = 0; j < 4; j++)
#pragma unroll
            for (int t = 0; t < 4; t++) acc[i][j][t] = 0.f;

    const uint32_t a4r = (uint32_t)((wm * 64 + (lane & 15)) * SROWB + (lane >> 4) * 16);
    const uint32_t b4r = (uint32_t)((wn * 32 + (lane & 7)) * SROWB + ((lane >> 3) & 1) * 16 + (lane >> 4) * 32);

    const int nchunks = K / 32;

    // cp.async stage loader: 2048 x 16B per chunk, 8 per thread
    auto stage_load = [&](int k0, uint32_t sst) {
#pragma unroll
        for (int it = 0; it < 8; it++) {
            int idx = tid + it * 256;
            int plane = idx >> 9;           // 0..3
            int rem = idx & 511;
            int row = rem >> 2;             // 0..127
            int q = rem & 3;                // 16B quarter
            const uint16_t* src;
            if (plane == 0)      src = Ah + (size_t)(bm + row) * lda + k0 + q * 8;
            else if (plane == 1) src = Al + (size_t)(bm + row) * lda + k0 + q * 8;
            else if (plane == 2) src = Bh + (size_t)(bn + row) * ldb + k0 + q * 8;
            else                 src = Bl + (size_t)(bn + row) * ldb + k0 + q * 8;
            cp16(sst + (uint32_t)(plane * GPLANE + row * SROWB + q * 16), src);
        }
        CP_COMMIT();
    };

    stage_load(0, sbase);
    if (nchunks > 1) stage_load(32, sbase + GSTAGE);

    for (int c = 0; c < nchunks; c++) {
        if (c + 1 < nchunks) { CP_WAIT1(); } else { CP_WAIT0(); }
        __syncthreads();
        const uint32_t ss = sbase + (uint32_t)((c & 1) * GSTAGE);

        uint32_t bh4[4][4], bl4[4][4];
#pragma unroll
        for (int nt = 0; nt < 4; nt++) {
            ldsm_x4(bh4[nt], ss + b4r + nt * 8 * SROWB + PBH);
            ldsm_x4(bl4[nt], ss + b4r + nt * 8 * SROWB + PBL);
        }
#pragma unroll
        for (int ks = 0; ks < 2; ks++) {
            uint32_t ah[4][4], al[4][4];
#pragma unroll
            for (int mt = 0; mt < 4; mt++) {
                ldsm_x4(ah[mt], ss + a4r + mt * 16 * SROWB + ks * 32 + PAH);
                ldsm_x4(al[mt], ss + a4r + mt * 16 * SROWB + ks * 32 + PAL);
            }
#pragma unroll
            for (int mt = 0; mt < 4; mt++)
#pragma unroll
                for (int nt = 0; nt < 4; nt++) {
                    mma_bf16(acc[mt][nt], ah[mt], &bh4[nt][2 * ks]);
                    mma_bf16(acc[mt][nt], ah[mt], &bl4[nt][2 * ks]);
                    mma_bf16(acc[mt][nt], al[mt], &bh4[nt][2 * ks]);
                }
        }
        __syncthreads();
        if (c + 2 < nchunks) stage_load((c + 2) * 32, sbase + (uint32_t)((c & 1) * GSTAGE));
    }

    // ---- epilogue -----------------------------------------------------------
    uint16_t *ph = P0h, *pl = P0l;
    if (MODE == 2) {
        const int part = bn >> 10;
        ph = (part == 0) ? P0h : (part == 1) ? P1h : P2h;
        pl = (part == 0) ? P0l : (part == 1) ? P1l : P2l;
    }
#pragma unroll
    for (int mt = 0; mt < 4; mt++) {
#pragma unroll
        for (int nt = 0; nt < 4; nt++) {
            const int m0 = bm + wm * 64 + mt * 16 + (lane >> 2);
            const int n0 = bn + wn * 32 + nt * 8 + 2 * (lane & 3);
            float2 v0 = make_float2(acc[mt][nt][0], acc[mt][nt][1]);
            float2 v1 = make_float2(acc[mt][nt][2], acc[mt][nt][3]);
            if (MODE == 0) {
                float2 bb = *(const float2*)(bias + n0);
                float2 r0 = *(const float2*)(res + (size_t)m0 * ldr + n0);
                float2 r1 = *(const float2*)(res + (size_t)(m0 + 8) * ldr + n0);
                v0.x += bb.x + r0.x; v0.y += bb.y + r0.y;
                v1.x += bb.x + r1.x; v1.y += bb.y + r1.y;
                *(float2*)(C + (size_t)m0 * ldc + n0) = v0;
                *(float2*)(C + (size_t)(m0 + 8) * ldc + n0) = v1;
            } else {
                if (MODE == 2) {
                    float2 bb = *(const float2*)(bias + n0);
                    v0.x += bb.x; v0.y += bb.y;
                    v1.x += bb.x; v1.y += bb.y;
                } else {
                    v0.x *= scale; v0.y *= scale;
                    v1.x *= scale; v1.y *= scale;
                }
                const int nc = (MODE == 2) ? (n0 & 1023) : n0;
                uint32_t h0, l0, h1, l1;
                pack2(v0.x, v0.y, h0, l0);
                pack2(v1.x, v1.y, h1, l1);
                *(uint32_t*)(ph + (size_t)m0 * ldp + nc) = h0;
                *(uint32_t*)(pl + (size_t)m0 * ldp + nc) = l0;
                *(uint32_t*)(ph + (size_t)(m0 + 8) * ldp + nc) = h1;
                *(uint32_t*)(pl + (size_t)(m0 + 8) * ldp + nc) = l1;
            }
        }
    }
}

// ======================= HMMA flash attention (cp.async 2-stage) =============
#define TROWB 144
#define FPLANE (64 * TROWB)         // 9216
#define FSTAGE (4 * FPLANE)         // 36864
#define FLASH_SMEM (2 * FSTAGE)     // 73728
#define QKH 0
#define QKL FPLANE
#define QVH (2 * FPLANE)
#define QVL (3 * FPLANE)
#define NKT (SEQ / 64)              // 32

__global__ __launch_bounds__(128)
void flash_bf16(const uint16_t* __restrict__ Qh, const uint16_t* __restrict__ Ql,
                const uint16_t* __restrict__ Kh, const uint16_t* __restrict__ Kl,
                const uint16_t* __restrict__ Vh, const uint16_t* __restrict__ Vl,
                uint16_t* __restrict__ Oh, uint16_t* __restrict__ Ol)
{
    extern __shared__ char smem[];
    const uint32_t sbase = smem_u32(smem);

    const int tid  = threadIdx.x;
    const int lane = tid & 31;
    const int w    = tid >> 5;
    const int h = blockIdx.y;
    const int b = blockIdx.z;
    const int bq = blockIdx.x * 64;

    const size_t qrow0 = (size_t)(b * SEQ + bq);
    const size_t krow0 = (size_t)b * SEQ;
    const int hc = h * HDIM;

    // ---- stage Q planes into stage-0 K region, extract A fragments ----------
    {
        const int r  = tid >> 1;
        const int c8h = (tid & 1) * 4;
#pragma unroll
        for (int g = 0; g < 4; g++) {
            const uint16_t* src = Qh + (qrow0 + r) * E_DIM + hc + (c8h + g) * 8;
            *(uint4*)(smem + r * TROWB + (c8h + g) * 16 + QKH) = *(const uint4*)src;
            src = Ql + (qrow0 + r) * E_DIM + hc + (c8h + g) * 8;
            *(uint4*)(smem + r * TROWB + (c8h + g) * 16 + QKL) = *(const uint4*)src;
        }
    }
    __syncthreads();

    uint32_t qh[4][4], ql[4][4];
    {
        const uint32_t a_off = sbase + (uint32_t)((w * 16 + (lane & 15)) * TROWB + (lane >> 4) * 16);
#pragma unroll
        for (int ks = 0; ks < 4; ks++) {
            ldsm_x4(qh[ks], a_off + QKH + ks * 32);
            ldsm_x4(ql[ks], a_off + QKL + ks * 32);
        }
    }
    __syncthreads();   // all warps done reading Q before cp.async overwrites

    float o[8][4];
#pragma unroll
    for (int nt = 0; nt < 8; nt++)
#pragma unroll
        for (int t = 0; t < 4; t++) o[nt][t] = 0.f;
    float mrow[2] = {-1e30f, -1e30f};
    float lrow[2] = {0.f, 0.f};

    const uint32_t kb4r = (uint32_t)((lane & 7) * TROWB + ((lane >> 3) & 1) * 16 + (lane >> 4) * 32);
    const uint32_t vb4r = (uint32_t)(((lane & 7) + ((lane >> 3) & 1) * 8) * TROWB + (lane >> 4) * 16);

    // cp.async K/V tile loader: 2048 x 16B, 16 per thread
    auto stage_kv = [&](int j0, uint32_t sst) {
#pragma unroll
        for (int it = 0; it < 16; it++) {
            int idx = tid + it * 128;
            int plane = idx >> 9;       // 0..3
            int rem = idx & 511;
            int row = rem >> 3;         // 0..63
            int q = rem & 7;
            const size_t g = (krow0 + j0 + row) * (size_t)E_DIM + hc + q * 8;
            const uint16_t* src;
            if (plane == 0)      src = Kh + g;
            else if (plane == 1) src = Kl + g;
            else if (plane == 2) src = Vh + g;
            else                 src = Vl + g;
            cp16(sst + (uint32_t)(plane * FPLANE + row * TROWB + q * 16), src);
        }
        CP_COMMIT();
    };

    stage_kv(0, sbase);
    stage_kv(64, sbase + FSTAGE);

    for (int c = 0; c < NKT; c++) {
        if (c + 1 < NKT) { CP_WAIT1(); } else { CP_WAIT0(); }
        __syncthreads();
        const uint32_t ss = sbase + (uint32_t)((c & 1) * FSTAGE);

        // ---- S = Q K^T ------------------------------------------------------
        float s[8][4];
#pragma unroll
        for (int nt = 0; nt < 8; nt++)
#pragma unroll
            for (int t = 0; t < 4; t++) s[nt][t] = 0.f;
#pragma unroll
        for (int ksp = 0; ksp < 2; ksp++) {
#pragma unroll
            for (int nt = 0; nt < 8; nt++) {
                uint32_t bd = ss + kb4r + (uint32_t)(nt * 8 * TROWB + ksp * 64);
                uint32_t bh[4], bl[4];
                ldsm_x4(bh, bd + QKH);
                ldsm_x4(bl, bd + QKL);
                mma_bf16(s[nt], qh[2 * ksp],     bh);
                mma_bf16(s[nt], qh[2 * ksp],     bl);
                mma_bf16(s[nt], ql[2 * ksp],     bh);
                mma_bf16(s[nt], qh[2 * ksp + 1], bh + 2);
                mma_bf16(s[nt], qh[2 * ksp + 1], bl + 2);
                mma_bf16(s[nt], ql[2 * ksp + 1], bh + 2);
            }
        }

        // ---- online softmax -------------------------------------------------
#pragma unroll
        for (int rr = 0; rr < 2; rr++) {
            const int off = 2 * rr;
            float mx = s[0][off];
#pragma unroll
            for (int nt = 0; nt < 8; nt++) {
                mx = fmaxf(mx, s[nt][off]);
                mx = fmaxf(mx, s[nt][off + 1]);
            }
            mx = fmaxf(mx, __shfl_xor_sync(0xffffffffu, mx, 1));
            mx = fmaxf(mx, __shfl_xor_sync(0xffffffffu, mx, 2));
            float mnew = fmaxf(mrow[rr], mx);
            float sc = __expf(mrow[rr] - mnew);
            mrow[rr] = mnew;
            float sum = 0.f;
#pragma unroll
            for (int nt = 0; nt < 8; nt++) {
                s[nt][off]     = __expf(s[nt][off]     - mnew);
                s[nt][off + 1] = __expf(s[nt][off + 1] - mnew);
                sum += s[nt][off] + s[nt][off + 1];
            }
            sum += __shfl_xor_sync(0xffffffffu, sum, 1);
            sum += __shfl_xor_sync(0xffffffffu, sum, 2);
            lrow[rr] = lrow[rr] * sc + sum;
#pragma unroll
            for (int nt = 0; nt < 8; nt++) {
                o[nt][off]     *= sc;
                o[nt][off + 1] *= sc;
            }
        }

        // ---- O += P V -------------------------------------------------------
#pragma unroll
        for (int ks = 0; ks < 4; ks++) {
            uint32_t pa[4], pl2[4];
            pack2(s[2 * ks][0],     s[2 * ks][1],     pa[0], pl2[0]);
            pack2(s[2 * ks][2],     s[2 * ks][3],     pa[1], pl2[1]);
            pack2(s[2 * ks + 1][0], s[2 * ks + 1][1], pa[2], pl2[2]);
            pack2(s[2 * ks + 1][2], s[2 * ks + 1][3], pa[3], pl2[3]);
#pragma unroll
            for (int nt2 = 0; nt2 < 4; nt2++) {
                uint32_t vd = ss + vb4r + (uint32_t)(ks * 16 * TROWB + nt2 * 32);
                uint32_t bh[4], bl[4];
                ldsm_x4t(bh, vd + QVH);
                ldsm_x4t(bl, vd + QVL);
                mma_bf16(o[2 * nt2], pa, bh);
                mma_bf16(o[2 * nt2], pa, bl);
                mma_bf16(o[2 * nt2], pl2, bh);
                mma_bf16(o[2 * nt2 + 1], pa, bh + 2);
                mma_bf16(o[2 * nt2 + 1], pa, bl + 2);
                mma_bf16(o[2 * nt2 + 1], pl2, bh + 2);
            }
        }
        __syncthreads();
        if (c + 2 < NKT) stage_kv((c + 2) * 64, sbase + (uint32_t)((c & 1) * FSTAGE));
    }

    // ---- epilogue: write O planes -------------------------------------------
    const float inv0 = 1.f / lrow[0];
    const float inv1 = 1.f / lrow[1];
    const size_t m0 = qrow0 + w * 16 + (lane >> 2);
#pragma unroll
    for (int nt = 0; nt < 8; nt++) {
        const int n = hc + nt * 8 + 2 * (lane & 3);
        uint32_t h0, l0, h1, l1;
        pack2(o[nt][0] * inv0, o[nt][1] * inv0, h0, l0);
        pack2(o[nt][2] * inv1, o[nt][3] * inv1, h1, l1);
        *(uint32_t*)(Oh + m0 * E_DIM + n) = h0;
        *(uint32_t*)(Ol + m0 * E_DIM + n) = l0;
        *(uint32_t*)(Oh + (m0 + 8) * E_DIM + n) = h1;
        *(uint32_t*)(Ol + (m0 + 8) * E_DIM + n) = l1;
    }
}

// ---------------- launcher ---------------------------------------------------
extern "C" void kernel_launch(void* const* d_in, const int* in_sizes, int n_in,
                              void* d_out, int out_size)
{
    (void)in_sizes; (void)n_in; (void)out_size;
    const float* x    = (const float*)d_in[0];
    const float* rot  = (const float*)d_in[1];
    const float* ent  = (const float*)d_in[2];
    const float* qkvw = (const float*)d_in[3];
    const float* qkvb = (const float*)d_in[4];
    const float* outw = (const float*)d_in[5];
    const float* outb = (const float*)d_in[6];
    float* out = (float*)d_out;

    uint16_t *xb, *wqkv, *rotT, *entT, *wout, *aq, *ak, *v, *qp, *kp, *ob;
    cudaGetSymbolAddress((void**)&xb,   g_xb);
    cudaGetSymbolAddress((void**)&wqkv, g_wqkv);
    cudaGetSymbolAddress((void**)&rotT, g_rotT);
    cudaGetSymbolAddress((void**)&entT, g_entT);
    cudaGetSymbolAddress((void**)&wout, g_wout);
    cudaGetSymbolAddress((void**)&aq,   g_aq);
    cudaGetSymbolAddress((void**)&ak,   g_ak);
    cudaGetSymbolAddress((void**)&v,    g_v);
    cudaGetSymbolAddress((void**)&qp,   g_qp);
    cudaGetSymbolAddress((void**)&kp,   g_kp);
    cudaGetSymbolAddress((void**)&ob,   g_ob);

    const int NX  = MROWS * E_DIM;
    const int NW3 = 3 * E_DIM * E_DIM;
    const int NW  = E_DIM * E_DIM;

    cudaFuncSetAttribute(hgemm_bf16<0>, cudaFuncAttributeMaxDynamicSharedMemorySize, GEMM_SMEM);
    cudaFuncSetAttribute(hgemm_bf16<1>, cudaFuncAttributeMaxDynamicSharedMemorySize, GEMM_SMEM);
    cudaFuncSetAttribute(hgemm_bf16<2>, cudaFuncAttributeMaxDynamicSharedMemorySize, GEMM_SMEM);
    cudaFuncSetAttribute(flash_bf16,    cudaFuncAttributeMaxDynamicSharedMemorySize, FLASH_SMEM);

    // 0) one-time splits
    conv_split<<<512, 256>>>(x,    xb,   NX);
    conv_split<<<512, 256>>>(qkvw, wqkv, NW3);
    conv_split<<<256, 256>>>(outw, wout, NW);
    convT_split<<<dim3(32, 32), dim3(32, 8)>>>(rot, rotT);
    convT_split<<<dim3(32, 32), dim3(32, 8)>>>(ent, entT);

    // 1) qkv = x @ qkv_w^T + qkv_b  ->  q/k/v planes
    hgemm_bf16<2><<<dim3(3 * E_DIM / 128, MROWS / 128), 256, GEMM_SMEM>>>(
        xb, xb + NX, E_DIM, wqkv, wqkv + NW3, E_DIM,
        qkvb, nullptr, 0, nullptr, 0,
        aq, aq + NX, ak, ak + NX, v, v + NX, E_DIM, 1.f, E_DIM);

    // 2) q' = q @ rotation (pre-scaled 1/8) -> Q planes
    hgemm_bf16<1><<<dim3(E_DIM / 128, MROWS / 128), 256, GEMM_SMEM>>>(
        aq, aq + NX, E_DIM, rotT, rotT + NW, E_DIM,
        nullptr, nullptr, 0, nullptr, 0,
        qp, qp + NX, nullptr, nullptr, nullptr, nullptr, E_DIM, 0.125f, E_DIM);

    // 3) k' = k @ entangle -> K planes
    hgemm_bf16<1><<<dim3(E_DIM / 128, MROWS / 128), 256, GEMM_SMEM>>>(
        ak, ak + NX, E_DIM, entT, entT + NW, E_DIM,
        nullptr, nullptr, 0, nullptr, 0,
        kp, kp + NX, nullptr, nullptr, nullptr, nullptr, E_DIM, 1.f, E_DIM);

    // 4) attention -> O planes
    flash_bf16<<<dim3(SEQ / 64, NHEAD, BATCH), 128, FLASH_SMEM>>>(
        qp, qp + NX, kp, kp + NX, v, v + NX, ob, ob + NX);

    // 5) out = O @ out_w^T + out_b + x
    hgemm_bf16<0><<<dim3(E_DIM / 128, MROWS / 128), 256, GEMM_SMEM>>>(
        ob, ob + NX, E_DIM, wout, wout + NW, E_DIM,
        outb, x, E_DIM, out, E_DIM,
        nullptr, nullptr, nullptr, nullptr, nullptr, nullptr, 0, 1.f, E_DIM);
}